// round 6
// baseline (speedup 1.0000x reference)
#include <cuda_runtime.h>
#include <cuda_bf16.h>
#include <math.h>
#include <stdint.h>

#define D_MODEL 1024
#define N_HEADS 16
#define HEAD_DIM 64
#define B_SIZE 4
#define T_LEN 2048
#define TOKENS (B_SIZE * T_LEN)   // 8192

// Scratch (device globals: allocation-free per harness rules)
__device__ float g_qkv[(size_t)TOKENS * 3 * D_MODEL];   // [B,T,3,H,Dh] = 96 MB
__device__ float g_attn[(size_t)TOKENS * D_MODEL];      // [B,T,C]     = 32 MB

__device__ __forceinline__ uint32_t pk_bf(__nv_bfloat16 a, __nv_bfloat16 b) {
    return (uint32_t)__bfloat16_as_ushort(a) | ((uint32_t)__bfloat16_as_ushort(b) << 16);
}

__device__ __forceinline__ void mma_bf16(float* c, const uint32_t* a, const uint32_t* b) {
    asm volatile(
        "mma.sync.aligned.m16n8k16.row.col.f32.bf16.bf16.f32 "
        "{%0,%1,%2,%3}, {%4,%5,%6,%7}, {%8,%9}, {%0,%1,%2,%3};"
        : "+f"(c[0]), "+f"(c[1]), "+f"(c[2]), "+f"(c[3])
        : "r"(a[0]), "r"(a[1]), "r"(a[2]), "r"(a[3]), "r"(b[0]), "r"(b[1]));
}

// ---------------------------------------------------------------------------
// Tensor-core GEMM via mma.sync (HMMA): C[M,N] = A[M,K] @ W[N,K]^T + bias[N]
// fp32 in/out; split-bf16 (hi+lo, 3 MMA passes) for fp32-class accuracy.
// CTA 128x128, BK=32, 256 threads (8 warps, 2x4; 64x32 C per warp).
// ---------------------------------------------------------------------------
#define BK 32
#define LDS_STRIDE 40   // bf16 elements per smem row (32 + 8 pad)

__global__ __launch_bounds__(256)
void gemm_tc(const float* __restrict__ A, const float* __restrict__ W,
             const float* __restrict__ bias, float* __restrict__ C,
             int M, int N, int K)
{
    __shared__ __nv_bfloat16 Ah[128 * LDS_STRIDE];
    __shared__ __nv_bfloat16 Al[128 * LDS_STRIDE];
    __shared__ __nv_bfloat16 Bh[128 * LDS_STRIDE];
    __shared__ __nv_bfloat16 Bl[128 * LDS_STRIDE];

    const int tid  = threadIdx.x;
    const int lane = tid & 31;
    const int w    = tid >> 5;         // 0..7
    const int wm   = w >> 2;           // 0..1  (64-row band)
    const int wn   = w & 3;            // 0..3  (32-col band)
    const int g    = lane >> 2;        // 0..7
    const int t    = lane & 3;         // 0..3
    const int brow = blockIdx.y * 128;
    const int bcol = blockIdx.x * 128;

    float acc[4][4][4];
    #pragma unroll
    for (int i = 0; i < 4; i++)
        #pragma unroll
        for (int j = 0; j < 4; j++)
            #pragma unroll
            for (int e = 0; e < 4; e++) acc[i][j][e] = 0.f;

    for (int k0 = 0; k0 < K; k0 += BK) {
        // ---- global fp32 -> split bf16 hi/lo -> smem ----
        #pragma unroll
        for (int i = 0; i < 4; i++) {
            int idx = tid + i * 256;        // 0..1023 float4 granules
            int row = idx >> 3;             // 0..127
            int col = (idx & 7) << 2;       // 0,4,...,28
            int so  = row * LDS_STRIDE + col;
            {
                float4 f = *(const float4*)(A + (size_t)(brow + row) * K + k0 + col);
                float v[4] = {f.x, f.y, f.z, f.w};
                __nv_bfloat16 h[4], l[4];
                #pragma unroll
                for (int j = 0; j < 4; j++) {
                    h[j] = __float2bfloat16(v[j]);
                    l[j] = __float2bfloat16(v[j] - __bfloat162float(h[j]));
                }
                *(uint2*)&Ah[so] = make_uint2(pk_bf(h[0], h[1]), pk_bf(h[2], h[3]));
                *(uint2*)&Al[so] = make_uint2(pk_bf(l[0], l[1]), pk_bf(l[2], l[3]));
            }
            {
                float4 f = *(const float4*)(W + (size_t)(bcol + row) * K + k0 + col);
                float v[4] = {f.x, f.y, f.z, f.w};
                __nv_bfloat16 h[4], l[4];
                #pragma unroll
                for (int j = 0; j < 4; j++) {
                    h[j] = __float2bfloat16(v[j]);
                    l[j] = __float2bfloat16(v[j] - __bfloat162float(h[j]));
                }
                *(uint2*)&Bh[so] = make_uint2(pk_bf(h[0], h[1]), pk_bf(h[2], h[3]));
                *(uint2*)&Bl[so] = make_uint2(pk_bf(l[0], l[1]), pk_bf(l[2], l[3]));
            }
        }
        __syncthreads();

        // ---- two k16 steps per chunk ----
        #pragma unroll
        for (int ks = 0; ks < BK; ks += 16) {
            uint32_t ah[4][4], al[4][4], bh[4][2], bl[4][2];

            #pragma unroll
            for (int mt = 0; mt < 4; mt++) {
                int r0 = (wm * 64 + mt * 16 + g) * LDS_STRIDE + ks + t * 2;
                int r8 = r0 + 8 * LDS_STRIDE;
                ah[mt][0] = *(const uint32_t*)&Ah[r0];
                ah[mt][1] = *(const uint32_t*)&Ah[r8];
                ah[mt][2] = *(const uint32_t*)&Ah[r0 + 8];
                ah[mt][3] = *(const uint32_t*)&Ah[r8 + 8];
                al[mt][0] = *(const uint32_t*)&Al[r0];
                al[mt][1] = *(const uint32_t*)&Al[r8];
                al[mt][2] = *(const uint32_t*)&Al[r0 + 8];
                al[mt][3] = *(const uint32_t*)&Al[r8 + 8];
            }
            #pragma unroll
            for (int nt = 0; nt < 4; nt++) {
                int c0 = (wn * 32 + nt * 8 + g) * LDS_STRIDE + ks + t * 2;
                bh[nt][0] = *(const uint32_t*)&Bh[c0];
                bh[nt][1] = *(const uint32_t*)&Bh[c0 + 8];
                bl[nt][0] = *(const uint32_t*)&Bl[c0];
                bl[nt][1] = *(const uint32_t*)&Bl[c0 + 8];
            }

            #pragma unroll
            for (int mt = 0; mt < 4; mt++)
                #pragma unroll
                for (int nt = 0; nt < 4; nt++) {
                    mma_bf16(acc[mt][nt], ah[mt], bh[nt]);   // hi*hi
                    mma_bf16(acc[mt][nt], ah[mt], bl[nt]);   // hi*lo
                    mma_bf16(acc[mt][nt], al[mt], bh[nt]);   // lo*hi
                }
        }
        __syncthreads();
    }

    // ---- epilogue: bias + store ----
    #pragma unroll
    for (int mt = 0; mt < 4; mt++) {
        int r0 = brow + wm * 64 + mt * 16 + g;
        #pragma unroll
        for (int nt = 0; nt < 4; nt++) {
            int c0 = bcol + wn * 32 + nt * 8 + t * 2;
            float b0 = bias[c0], b1 = bias[c0 + 1];
            *(float2*)(C + (size_t)r0 * N + c0) =
                make_float2(acc[mt][nt][0] + b0, acc[mt][nt][1] + b1);
            *(float2*)(C + (size_t)(r0 + 8) * N + c0) =
                make_float2(acc[mt][nt][2] + b0, acc[mt][nt][3] + b1);
        }
    }
}

// ---------------------------------------------------------------------------
// Causal flash attention, fp32 (unchanged; fp32-FMA bound — next target).
// ---------------------------------------------------------------------------
#define TQ 128
#define TK 16

__global__ __launch_bounds__(128)
void flash_attn(const float* __restrict__ qkv, float* __restrict__ out)
{
    const int b   = blockIdx.z;
    const int h   = blockIdx.y;
    const int q0  = blockIdx.x * TQ;
    const int tid = threadIdx.x;
    const int q   = q0 + tid;
    const size_t tok = 3 * D_MODEL;   // 3072 floats per token

    const float* qp = qkv + (size_t)(b * T_LEN + q) * tok + h * HEAD_DIM;
    float qr[64];
    #pragma unroll
    for (int d = 0; d < 64; d++) qr[d] = qp[d] * 0.125f;   // fold 1/sqrt(64)

    float o[64];
    #pragma unroll
    for (int d = 0; d < 64; d++) o[d] = 0.f;
    float m = -INFINITY, l = 0.f;

    __shared__ float Ks[TK][64];
    __shared__ float Vs[TK][64];

    const float* kb = qkv + (size_t)b * T_LEN * tok + 1 * D_MODEL + h * HEAD_DIM;
    const float* vb = qkv + (size_t)b * T_LEN * tok + 2 * D_MODEL + h * HEAD_DIM;

    for (int k0 = 0; k0 < q0 + TQ; k0 += TK) {
        #pragma unroll
        for (int i = 0; i < 2; i++) {
            int idx = tid + i * 128;
            int row = idx >> 4;
            int cv  = (idx & 15) << 2;
            *(float4*)&Ks[row][cv] = *(const float4*)(kb + (size_t)(k0 + row) * tok + cv);
            *(float4*)&Vs[row][cv] = *(const float4*)(vb + (size_t)(k0 + row) * tok + cv);
        }
        __syncthreads();

        float s[TK];
        #pragma unroll
        for (int j = 0; j < TK; j++) {
            float acc = 0.f;
            #pragma unroll
            for (int d = 0; d < 64; d++) acc = fmaf(qr[d], Ks[j][d], acc);
            s[j] = (k0 + j <= q) ? acc : -INFINITY;
        }

        float mt = m;
        #pragma unroll
        for (int j = 0; j < TK; j++) mt = fmaxf(mt, s[j]);
        float corr = __expf(m - mt);
        l *= corr;
        #pragma unroll
        for (int d = 0; d < 64; d++) o[d] *= corr;
        #pragma unroll
        for (int j = 0; j < TK; j++) {
            float p = __expf(s[j] - mt);
            l += p;
            #pragma unroll
            for (int d = 0; d < 64; d++) o[d] = fmaf(p, Vs[j][d], o[d]);
        }
        m = mt;
        __syncthreads();
    }

    const float inv = 1.f / l;
    float* op = out + (size_t)(b * T_LEN + q) * D_MODEL + h * HEAD_DIM;
    #pragma unroll
    for (int d = 0; d < 64; d++) op[d] = o[d] * inv;
}

// ---------------------------------------------------------------------------
extern "C" void kernel_launch(void* const* d_in, const int* in_sizes, int n_in,
                              void* d_out, int out_size)
{
    const float *x = nullptr, *w_qkv = nullptr, *b_qkv = nullptr,
                *w_out = nullptr, *b_out = nullptr;
    for (int i = 0; i < n_in; i++) {
        switch (in_sizes[i]) {
            case 8388608: x     = (const float*)d_in[i]; break;
            case 3145728: w_qkv = (const float*)d_in[i]; break;
            case 3072:    b_qkv = (const float*)d_in[i]; break;
            case 1048576: w_out = (const float*)d_in[i]; break;
            case 1024:    b_out = (const float*)d_in[i]; break;
            default: break;
        }
    }
    float* out = (float*)d_out;

    float *qkv_buf = nullptr, *attn_buf = nullptr;
    cudaGetSymbolAddress((void**)&qkv_buf, g_qkv);
    cudaGetSymbolAddress((void**)&attn_buf, g_attn);

    // 1) QKV projection: [8192,1024] @ [3072,1024]^T + b -> [8192,3072]
    gemm_tc<<<dim3(3 * D_MODEL / 128, TOKENS / 128), 256>>>(
        x, w_qkv, b_qkv, qkv_buf, TOKENS, 3 * D_MODEL, D_MODEL);

    // 2) Causal flash attention -> [B,T,C]
    flash_attn<<<dim3(T_LEN / TQ, N_HEADS, B_SIZE), TQ>>>(qkv_buf, attn_buf);

    // 3) Output projection: [8192,1024] @ [1024,1024]^T + b -> d_out
    gemm_tc<<<dim3(D_MODEL / 128, TOKENS / 128), 256>>>(
        attn_buf, w_out, b_out, out, TOKENS, D_MODEL, D_MODEL);
}

// round 7
// speedup vs baseline: 1.7132x; 1.7132x over previous
#include <cuda_runtime.h>
#include <cuda_bf16.h>
#include <math.h>
#include <stdint.h>

#define D_MODEL 1024
#define N_HEADS 16
#define HEAD_DIM 64
#define B_SIZE 4
#define T_LEN 2048
#define TOKENS (B_SIZE * T_LEN)   // 8192

// ---------------- scratch (device globals; allocation-free) ----------------
__device__ float g_qkv[(size_t)TOKENS * 3 * D_MODEL];    // 96 MB
__device__ float g_attn[(size_t)TOKENS * D_MODEL];       // 32 MB
__device__ __nv_bfloat16 g_xh[(size_t)TOKENS * D_MODEL], g_xl[(size_t)TOKENS * D_MODEL];
__device__ __nv_bfloat16 g_wqh[(size_t)3 * D_MODEL * D_MODEL], g_wql[(size_t)3 * D_MODEL * D_MODEL];
__device__ __nv_bfloat16 g_woh[(size_t)D_MODEL * D_MODEL], g_wol[(size_t)D_MODEL * D_MODEL];
__device__ __nv_bfloat16 g_ath[(size_t)TOKENS * D_MODEL], g_atl[(size_t)TOKENS * D_MODEL];

// ---------------------------- small helpers --------------------------------
__device__ __forceinline__ uint32_t smem_u32(const void* p) {
    uint32_t a;
    asm("{ .reg .u64 t; cvta.to.shared.u64 t, %1; cvt.u32.u64 %0, t; }"
        : "=r"(a) : "l"(p));
    return a;
}

__device__ __forceinline__ uint32_t pk_bf(__nv_bfloat16 a, __nv_bfloat16 b) {
    return (uint32_t)__bfloat16_as_ushort(a) | ((uint32_t)__bfloat16_as_ushort(b) << 16);
}

__device__ __forceinline__ void mma_bf16(float* c, const uint32_t* a, const uint32_t* b) {
    asm volatile(
        "mma.sync.aligned.m16n8k16.row.col.f32.bf16.bf16.f32 "
        "{%0,%1,%2,%3}, {%4,%5,%6,%7}, {%8,%9}, {%0,%1,%2,%3};"
        : "+f"(c[0]), "+f"(c[1]), "+f"(c[2]), "+f"(c[3])
        : "r"(a[0]), "r"(a[1]), "r"(a[2]), "r"(a[3]), "r"(b[0]), "r"(b[1]));
}

__device__ __forceinline__ void ldmx4(uint32_t r[4], uint32_t addr) {
    asm volatile("ldmatrix.sync.aligned.m8n8.x4.shared.b16 {%0,%1,%2,%3}, [%4];"
        : "=r"(r[0]), "=r"(r[1]), "=r"(r[2]), "=r"(r[3]) : "r"(addr));
}

// -------------------- pre-split: fp32 -> bf16 hi + lo ----------------------
__global__ __launch_bounds__(256)
void split_bf16(const float* __restrict__ src, __nv_bfloat16* __restrict__ hi,
                __nv_bfloat16* __restrict__ lo, int n4)
{
    int i = blockIdx.x * 256 + threadIdx.x;
    if (i >= n4) return;
    float4 f = ((const float4*)src)[i];
    float v[4] = {f.x, f.y, f.z, f.w};
    __nv_bfloat16 h[4], l[4];
    #pragma unroll
    for (int j = 0; j < 4; j++) {
        h[j] = __float2bfloat16(v[j]);
        l[j] = __float2bfloat16(v[j] - __bfloat162float(h[j]));
    }
    ((uint2*)hi)[i] = make_uint2(pk_bf(h[0], h[1]), pk_bf(h[2], h[3]));
    ((uint2*)lo)[i] = make_uint2(pk_bf(l[0], l[1]), pk_bf(l[2], l[3]));
}

// ---------------------------------------------------------------------------
// bf16 split GEMM: C[M,N] = A@W^T + bias, A/W given as bf16 (hi,lo) pairs.
// 3-term: Ah*Bh + Ah*Bl + Al*Bh. CTA 128x128, BK=32, 2-stage cp.async,
// ldmatrix fragments, 8 warps (2x4), warp tile 64x32.
// smem: per stage 4 buffers of 128 rows x 40 bf16 (stride-40 pad:
// conflict-free ldmatrix). 2 stages x 4 x 5120 el x 2B = 81920 B.
// ---------------------------------------------------------------------------
#define STG_E 20480       // elements per stage
#define BUF_E 5120        // elements per buffer (128*40)

__device__ __forceinline__ void stage_load(
    uint32_t sb, int s, int tid,
    const __nv_bfloat16* __restrict__ Ah_g, const __nv_bfloat16* __restrict__ Al_g,
    const __nv_bfloat16* __restrict__ Bh_g, const __nv_bfloat16* __restrict__ Bl_g,
    int brow, int bcol, int K, int k0)
{
    #pragma unroll
    for (int i = 0; i < 8; i++) {
        int c      = tid + i * 256;     // 0..2047 16B chunks
        int buf    = c >> 9;            // 0:Ah 1:Al 2:Bh 3:Bl
        int within = c & 511;
        int row    = within >> 2;
        int ch     = within & 3;
        const __nv_bfloat16* g = (buf == 0) ? Ah_g : (buf == 1) ? Al_g
                               : (buf == 2) ? Bh_g : Bl_g;
        int gr = ((buf < 2) ? brow : bcol) + row;
        const __nv_bfloat16* src = g + (size_t)gr * K + k0 + ch * 8;
        uint32_t dst = sb + (uint32_t)((s * STG_E + buf * BUF_E + row * 40 + ch * 8) * 2);
        asm volatile("cp.async.cg.shared.global [%0], [%1], 16;"
                     :: "r"(dst), "l"(src) : "memory");
    }
}

__global__ __launch_bounds__(256)
void gemm_bf16split(const __nv_bfloat16* __restrict__ Ah_g, const __nv_bfloat16* __restrict__ Al_g,
                    const __nv_bfloat16* __restrict__ Bh_g, const __nv_bfloat16* __restrict__ Bl_g,
                    const float* __restrict__ bias, float* __restrict__ C,
                    int M, int N, int K)
{
    extern __shared__ __nv_bfloat16 sm[];
    const uint32_t sb   = smem_u32(sm);
    const int tid  = threadIdx.x;
    const int lane = tid & 31;
    const int w    = tid >> 5;
    const int wm   = w >> 2;            // 0..1
    const int wn   = w & 3;             // 0..3
    const int sub  = lane & 7;
    const int matid = lane >> 3;
    const int brow = blockIdx.y * 128;
    const int bcol = blockIdx.x * 128;

    float acc[4][4][4];
    #pragma unroll
    for (int i = 0; i < 4; i++)
        #pragma unroll
        for (int j = 0; j < 4; j++)
            #pragma unroll
            for (int e = 0; e < 4; e++) acc[i][j][e] = 0.f;

    // per-thread fragment smem offsets (bytes), constant across chunks
    const int arow = wm * 64 + ((matid & 1) << 3) + sub;            // + mt*16
    const int acolb = ((matid >> 1) << 3);                          // + ks
    const int nrow = wn * 32 + ((matid >> 1) << 3) + sub;           // + ng*16
    const int ncolb = ((matid & 1) << 3);                           // + ks

    const int NC = K >> 5;   // K chunks of 32

    // prefetch stage 0
    stage_load(sb, 0, tid, Ah_g, Al_g, Bh_g, Bl_g, brow, bcol, K, 0);
    asm volatile("cp.async.commit_group;" ::: "memory");

    for (int kc = 0; kc < NC; kc++) {
        asm volatile("cp.async.wait_group 0;" ::: "memory");
        __syncthreads();

        if (kc + 1 < NC) {
            stage_load(sb, (kc + 1) & 1, tid, Ah_g, Al_g, Bh_g, Bl_g,
                       brow, bcol, K, (kc + 1) * 32);
            asm volatile("cp.async.commit_group;" ::: "memory");
        }

        const int s = kc & 1;
        const uint32_t sAh = sb + (uint32_t)((s * STG_E + 0 * BUF_E) * 2);
        const uint32_t sAl = sAh + BUF_E * 2;
        const uint32_t sBh = sAl + BUF_E * 2;
        const uint32_t sBl = sBh + BUF_E * 2;

        #pragma unroll
        for (int ks = 0; ks < 32; ks += 16) {
            uint32_t ah[4][4], al[4][4], bh[2][4], bl[2][4];

            #pragma unroll
            for (int mt = 0; mt < 4; mt++) {
                uint32_t off = (uint32_t)(((arow + mt * 16) * 40 + ks + acolb) * 2);
                ldmx4(ah[mt], sAh + off);
                ldmx4(al[mt], sAl + off);
            }
            #pragma unroll
            for (int ng = 0; ng < 2; ng++) {
                uint32_t off = (uint32_t)(((nrow + ng * 16) * 40 + ks + ncolb) * 2);
                ldmx4(bh[ng], sBh + off);
                ldmx4(bl[ng], sBl + off);
            }

            #pragma unroll
            for (int mt = 0; mt < 4; mt++)
                #pragma unroll
                for (int nt = 0; nt < 4; nt++) {
                    const uint32_t* bhp = &bh[nt >> 1][(nt & 1) * 2];
                    const uint32_t* blp = &bl[nt >> 1][(nt & 1) * 2];
                    mma_bf16(acc[mt][nt], ah[mt], bhp);   // hi*hi
                    mma_bf16(acc[mt][nt], ah[mt], blp);   // hi*lo
                    mma_bf16(acc[mt][nt], al[mt], bhp);   // lo*hi
                }
        }
        __syncthreads();
    }

    // ---- epilogue: bias + store (c-frag: row=lane>>2, col=2*(lane&3)) ----
    const int rg = lane >> 2;
    const int ct = lane & 3;
    #pragma unroll
    for (int mt = 0; mt < 4; mt++) {
        int r0 = brow + wm * 64 + mt * 16 + rg;
        #pragma unroll
        for (int nt = 0; nt < 4; nt++) {
            int c0 = bcol + wn * 32 + nt * 8 + ct * 2;
            float b0 = bias[c0], b1 = bias[c0 + 1];
            *(float2*)(C + (size_t)r0 * N + c0) =
                make_float2(acc[mt][nt][0] + b0, acc[mt][nt][1] + b1);
            *(float2*)(C + (size_t)(r0 + 8) * N + c0) =
                make_float2(acc[mt][nt][2] + b0, acc[mt][nt][3] + b1);
        }
    }
}

// ---------------------------------------------------------------------------
// Causal flash attention, fp32 (unchanged; next round's target).
// ---------------------------------------------------------------------------
#define TQ 128
#define TK 16

__global__ __launch_bounds__(128)
void flash_attn(const float* __restrict__ qkv, float* __restrict__ out)
{
    const int b   = blockIdx.z;
    const int h   = blockIdx.y;
    const int q0  = blockIdx.x * TQ;
    const int tid = threadIdx.x;
    const int q   = q0 + tid;
    const size_t tok = 3 * D_MODEL;   // 3072 floats per token

    const float* qp = qkv + (size_t)(b * T_LEN + q) * tok + h * HEAD_DIM;
    float qr[64];
    #pragma unroll
    for (int d = 0; d < 64; d++) qr[d] = qp[d] * 0.125f;

    float o[64];
    #pragma unroll
    for (int d = 0; d < 64; d++) o[d] = 0.f;
    float m = -INFINITY, l = 0.f;

    __shared__ float Ks[TK][64];
    __shared__ float Vs[TK][64];

    const float* kb = qkv + (size_t)b * T_LEN * tok + 1 * D_MODEL + h * HEAD_DIM;
    const float* vb = qkv + (size_t)b * T_LEN * tok + 2 * D_MODEL + h * HEAD_DIM;

    for (int k0 = 0; k0 < q0 + TQ; k0 += TK) {
        #pragma unroll
        for (int i = 0; i < 2; i++) {
            int idx = tid + i * 128;
            int row = idx >> 4;
            int cv  = (idx & 15) << 2;
            *(float4*)&Ks[row][cv] = *(const float4*)(kb + (size_t)(k0 + row) * tok + cv);
            *(float4*)&Vs[row][cv] = *(const float4*)(vb + (size_t)(k0 + row) * tok + cv);
        }
        __syncthreads();

        float s[TK];
        #pragma unroll
        for (int j = 0; j < TK; j++) {
            float acc = 0.f;
            #pragma unroll
            for (int d = 0; d < 64; d++) acc = fmaf(qr[d], Ks[j][d], acc);
            s[j] = (k0 + j <= q) ? acc : -INFINITY;
        }

        float mt = m;
        #pragma unroll
        for (int j = 0; j < TK; j++) mt = fmaxf(mt, s[j]);
        float corr = __expf(m - mt);
        l *= corr;
        #pragma unroll
        for (int d = 0; d < 64; d++) o[d] *= corr;
        #pragma unroll
        for (int j = 0; j < TK; j++) {
            float p = __expf(s[j] - mt);
            l += p;
            #pragma unroll
            for (int d = 0; d < 64; d++) o[d] = fmaf(p, Vs[j][d], o[d]);
        }
        m = mt;
        __syncthreads();
    }

    const float inv = 1.f / l;
    float* op = out + (size_t)(b * T_LEN + q) * D_MODEL + h * HEAD_DIM;
    #pragma unroll
    for (int d = 0; d < 64; d++) op[d] = o[d] * inv;
}

// ---------------------------------------------------------------------------
extern "C" void kernel_launch(void* const* d_in, const int* in_sizes, int n_in,
                              void* d_out, int out_size)
{
    const float *x = nullptr, *w_qkv = nullptr, *b_qkv = nullptr,
                *w_out = nullptr, *b_out = nullptr;
    for (int i = 0; i < n_in; i++) {
        switch (in_sizes[i]) {
            case 8388608: x     = (const float*)d_in[i]; break;
            case 3145728: w_qkv = (const float*)d_in[i]; break;
            case 3072:    b_qkv = (const float*)d_in[i]; break;
            case 1048576: w_out = (const float*)d_in[i]; break;
            case 1024:    b_out = (const float*)d_in[i]; break;
            default: break;
        }
    }
    float* out = (float*)d_out;

    float *qkv_buf, *attn_buf;
    __nv_bfloat16 *xh, *xl, *wqh, *wql, *woh, *wol, *ath, *atl;
    cudaGetSymbolAddress((void**)&qkv_buf, g_qkv);
    cudaGetSymbolAddress((void**)&attn_buf, g_attn);
    cudaGetSymbolAddress((void**)&xh, g_xh);  cudaGetSymbolAddress((void**)&xl, g_xl);
    cudaGetSymbolAddress((void**)&wqh, g_wqh); cudaGetSymbolAddress((void**)&wql, g_wql);
    cudaGetSymbolAddress((void**)&woh, g_woh); cudaGetSymbolAddress((void**)&wol, g_wol);
    cudaGetSymbolAddress((void**)&ath, g_ath); cudaGetSymbolAddress((void**)&atl, g_atl);

    cudaFuncSetAttribute(gemm_bf16split,
                         cudaFuncAttributeMaxDynamicSharedMemorySize, STG_E * 2 * 2 * 2);

    const int SMEM = STG_E * 2 * 2 * 2;   // 2 stages * 20480 el * 2B = 81920

    // 0) pre-split inputs to bf16 hi/lo
    {
        int n4x = TOKENS * D_MODEL / 4;
        split_bf16<<<(n4x + 255) / 256, 256>>>(x, xh, xl, n4x);
        int n4q = 3 * D_MODEL * D_MODEL / 4;
        split_bf16<<<(n4q + 255) / 256, 256>>>(w_qkv, wqh, wql, n4q);
        int n4o = D_MODEL * D_MODEL / 4;
        split_bf16<<<(n4o + 255) / 256, 256>>>(w_out, woh, wol, n4o);
    }

    // 1) QKV projection: [8192,1024] @ [3072,1024]^T + b -> [8192,3072]
    gemm_bf16split<<<dim3(3 * D_MODEL / 128, TOKENS / 128), 256, SMEM>>>(
        xh, xl, wqh, wql, b_qkv, qkv_buf, TOKENS, 3 * D_MODEL, D_MODEL);

    // 2) Causal flash attention -> [B,T,C]
    flash_attn<<<dim3(T_LEN / TQ, N_HEADS, B_SIZE), TQ>>>(qkv_buf, attn_buf);

    // 3) split attn, then output projection -> d_out
    {
        int n4a = TOKENS * D_MODEL / 4;
        split_bf16<<<(n4a + 255) / 256, 256>>>(attn_buf, ath, atl, n4a);
    }
    gemm_bf16split<<<dim3(D_MODEL / 128, TOKENS / 128), 256, SMEM>>>(
        ath, atl, woh, wol, b_out, out, TOKENS, D_MODEL, D_MODEL);
}

// round 8
// speedup vs baseline: 3.9751x; 2.3203x over previous
#include <cuda_runtime.h>
#include <cuda_bf16.h>
#include <math.h>
#include <stdint.h>

#define D_MODEL 1024
#define N_HEADS 16
#define HEAD_DIM 64
#define B_SIZE 4
#define T_LEN 2048
#define TOKENS (B_SIZE * T_LEN)   // 8192

// ---------------- scratch (device globals; allocation-free) ----------------
__device__ __nv_bfloat16 g_xh[(size_t)TOKENS * D_MODEL], g_xl[(size_t)TOKENS * D_MODEL];
__device__ __nv_bfloat16 g_wqh[(size_t)3 * D_MODEL * D_MODEL], g_wql[(size_t)3 * D_MODEL * D_MODEL];
__device__ __nv_bfloat16 g_woh[(size_t)D_MODEL * D_MODEL], g_wol[(size_t)D_MODEL * D_MODEL];
__device__ __nv_bfloat16 g_qkvh[(size_t)TOKENS * 3 * D_MODEL], g_qkvl[(size_t)TOKENS * 3 * D_MODEL];
__device__ __nv_bfloat16 g_ath[(size_t)TOKENS * D_MODEL], g_atl[(size_t)TOKENS * D_MODEL];

// ---------------------------- small helpers --------------------------------
__device__ __forceinline__ uint32_t smem_u32(const void* p) {
    uint32_t a;
    asm("{ .reg .u64 t; cvta.to.shared.u64 t, %1; cvt.u32.u64 %0, t; }"
        : "=r"(a) : "l"(p));
    return a;
}
__device__ __forceinline__ uint32_t pk_bf(__nv_bfloat16 a, __nv_bfloat16 b) {
    return (uint32_t)__bfloat16_as_ushort(a) | ((uint32_t)__bfloat16_as_ushort(b) << 16);
}
__device__ __forceinline__ void mma_bf16(float* c, const uint32_t* a, const uint32_t* b) {
    asm volatile(
        "mma.sync.aligned.m16n8k16.row.col.f32.bf16.bf16.f32 "
        "{%0,%1,%2,%3}, {%4,%5,%6,%7}, {%8,%9}, {%0,%1,%2,%3};"
        : "+f"(c[0]), "+f"(c[1]), "+f"(c[2]), "+f"(c[3])
        : "r"(a[0]), "r"(a[1]), "r"(a[2]), "r"(a[3]), "r"(b[0]), "r"(b[1]));
}
__device__ __forceinline__ void ldmx4(uint32_t r[4], uint32_t addr) {
    asm volatile("ldmatrix.sync.aligned.m8n8.x4.shared.b16 {%0,%1,%2,%3}, [%4];"
        : "=r"(r[0]), "=r"(r[1]), "=r"(r[2]), "=r"(r[3]) : "r"(addr));
}
__device__ __forceinline__ void ldmx4t(uint32_t r[4], uint32_t addr) {
    asm volatile("ldmatrix.sync.aligned.m8n8.x4.trans.shared.b16 {%0,%1,%2,%3}, [%4];"
        : "=r"(r[0]), "=r"(r[1]), "=r"(r[2]), "=r"(r[3]) : "r"(addr));
}
__device__ __forceinline__ void cpasync16(uint32_t dst, const void* src) {
    asm volatile("cp.async.cg.shared.global [%0], [%1], 16;" :: "r"(dst), "l"(src) : "memory");
}
__device__ __forceinline__ float ex2(float x) {
    float y; asm("ex2.approx.f32 %0, %1;" : "=f"(y) : "f"(x)); return y;
}

// -------------------- pre-split: fp32 -> bf16 hi + lo ----------------------
__global__ __launch_bounds__(256)
void split_bf16(const float* __restrict__ src, __nv_bfloat16* __restrict__ hi,
                __nv_bfloat16* __restrict__ lo, int n4)
{
    int i = blockIdx.x * 256 + threadIdx.x;
    if (i >= n4) return;
    float4 f = ((const float4*)src)[i];
    float v[4] = {f.x, f.y, f.z, f.w};
    __nv_bfloat16 h[4], l[4];
    #pragma unroll
    for (int j = 0; j < 4; j++) {
        h[j] = __float2bfloat16(v[j]);
        l[j] = __float2bfloat16(v[j] - __bfloat162float(h[j]));
    }
    ((uint2*)hi)[i] = make_uint2(pk_bf(h[0], h[1]), pk_bf(h[2], h[3]));
    ((uint2*)lo)[i] = make_uint2(pk_bf(l[0], l[1]), pk_bf(l[2], l[3]));
}

// ---------------------------------------------------------------------------
// bf16 split GEMM: C[M,N] = A@W^T + bias. OM=0: fp32 out; OM=1: bf16 hi/lo out.
// ---------------------------------------------------------------------------
#define STG_E 20480
#define BUF_E 5120

__device__ __forceinline__ void stage_load(
    uint32_t sb, int s, int tid,
    const __nv_bfloat16* __restrict__ Ah_g, const __nv_bfloat16* __restrict__ Al_g,
    const __nv_bfloat16* __restrict__ Bh_g, const __nv_bfloat16* __restrict__ Bl_g,
    int brow, int bcol, int K, int k0)
{
    #pragma unroll
    for (int i = 0; i < 8; i++) {
        int c      = tid + i * 256;
        int buf    = c >> 9;
        int within = c & 511;
        int row    = within >> 2;
        int ch     = within & 3;
        const __nv_bfloat16* g = (buf == 0) ? Ah_g : (buf == 1) ? Al_g
                               : (buf == 2) ? Bh_g : Bl_g;
        int gr = ((buf < 2) ? brow : bcol) + row;
        const __nv_bfloat16* src = g + (size_t)gr * K + k0 + ch * 8;
        uint32_t dst = sb + (uint32_t)((s * STG_E + buf * BUF_E + row * 40 + ch * 8) * 2);
        cpasync16(dst, src);
    }
}

template<int OM>
__global__ __launch_bounds__(256, 2)
void gemm_bf16split(const __nv_bfloat16* __restrict__ Ah_g, const __nv_bfloat16* __restrict__ Al_g,
                    const __nv_bfloat16* __restrict__ Bh_g, const __nv_bfloat16* __restrict__ Bl_g,
                    const float* __restrict__ bias, float* __restrict__ C,
                    __nv_bfloat16* __restrict__ Ch, __nv_bfloat16* __restrict__ Cl,
                    int M, int N, int K)
{
    extern __shared__ __nv_bfloat16 sm[];
    const uint32_t sb   = smem_u32(sm);
    const int tid  = threadIdx.x;
    const int lane = tid & 31;
    const int w    = tid >> 5;
    const int wm   = w >> 2;
    const int wn   = w & 3;
    const int sub  = lane & 7;
    const int matid = lane >> 3;
    const int brow = blockIdx.y * 128;
    const int bcol = blockIdx.x * 128;

    float acc[4][4][4];
    #pragma unroll
    for (int i = 0; i < 4; i++)
        #pragma unroll
        for (int j = 0; j < 4; j++)
            #pragma unroll
            for (int e = 0; e < 4; e++) acc[i][j][e] = 0.f;

    const int arow = wm * 64 + ((matid & 1) << 3) + sub;
    const int acolb = ((matid >> 1) << 3);
    const int nrow = wn * 32 + ((matid >> 1) << 3) + sub;
    const int ncolb = ((matid & 1) << 3);

    const int NC = K >> 5;

    stage_load(sb, 0, tid, Ah_g, Al_g, Bh_g, Bl_g, brow, bcol, K, 0);
    asm volatile("cp.async.commit_group;" ::: "memory");

    for (int kc = 0; kc < NC; kc++) {
        asm volatile("cp.async.wait_group 0;" ::: "memory");
        __syncthreads();

        if (kc + 1 < NC) {
            stage_load(sb, (kc + 1) & 1, tid, Ah_g, Al_g, Bh_g, Bl_g,
                       brow, bcol, K, (kc + 1) * 32);
            asm volatile("cp.async.commit_group;" ::: "memory");
        }

        const int s = kc & 1;
        const uint32_t sAh = sb + (uint32_t)((s * STG_E) * 2);
        const uint32_t sAl = sAh + BUF_E * 2;
        const uint32_t sBh = sAl + BUF_E * 2;
        const uint32_t sBl = sBh + BUF_E * 2;

        #pragma unroll
        for (int ks = 0; ks < 32; ks += 16) {
            uint32_t ah[4][4], al[4][4], bh[2][4], bl[2][4];
            #pragma unroll
            for (int mt = 0; mt < 4; mt++) {
                uint32_t off = (uint32_t)(((arow + mt * 16) * 40 + ks + acolb) * 2);
                ldmx4(ah[mt], sAh + off);
                ldmx4(al[mt], sAl + off);
            }
            #pragma unroll
            for (int ng = 0; ng < 2; ng++) {
                uint32_t off = (uint32_t)(((nrow + ng * 16) * 40 + ks + ncolb) * 2);
                ldmx4(bh[ng], sBh + off);
                ldmx4(bl[ng], sBl + off);
            }
            #pragma unroll
            for (int mt = 0; mt < 4; mt++)
                #pragma unroll
                for (int nt = 0; nt < 4; nt++) {
                    const uint32_t* bhp = &bh[nt >> 1][(nt & 1) * 2];
                    const uint32_t* blp = &bl[nt >> 1][(nt & 1) * 2];
                    mma_bf16(acc[mt][nt], ah[mt], bhp);
                    mma_bf16(acc[mt][nt], ah[mt], blp);
                    mma_bf16(acc[mt][nt], al[mt], bhp);
                }
        }
        __syncthreads();
    }

    const int rg = lane >> 2;
    const int ct = lane & 3;
    #pragma unroll
    for (int mt = 0; mt < 4; mt++) {
        int r0 = brow + wm * 64 + mt * 16 + rg;
        #pragma unroll
        for (int nt = 0; nt < 4; nt++) {
            int c0 = bcol + wn * 32 + nt * 8 + ct * 2;
            float b0 = bias[c0], b1 = bias[c0 + 1];
            float v00 = acc[mt][nt][0] + b0, v01 = acc[mt][nt][1] + b1;
            float v10 = acc[mt][nt][2] + b0, v11 = acc[mt][nt][3] + b1;
            if (OM == 0) {
                *(float2*)(C + (size_t)r0 * N + c0) = make_float2(v00, v01);
                *(float2*)(C + (size_t)(r0 + 8) * N + c0) = make_float2(v10, v11);
            } else {
                __nv_bfloat16 h00 = __float2bfloat16(v00), h01 = __float2bfloat16(v01);
                __nv_bfloat16 h10 = __float2bfloat16(v10), h11 = __float2bfloat16(v11);
                *(uint32_t*)(Ch + (size_t)r0 * N + c0) = pk_bf(h00, h01);
                *(uint32_t*)(Ch + (size_t)(r0 + 8) * N + c0) = pk_bf(h10, h11);
                *(uint32_t*)(Cl + (size_t)r0 * N + c0) = pk_bf(
                    __float2bfloat16(v00 - __bfloat162float(h00)),
                    __float2bfloat16(v01 - __bfloat162float(h01)));
                *(uint32_t*)(Cl + (size_t)(r0 + 8) * N + c0) = pk_bf(
                    __float2bfloat16(v10 - __bfloat162float(h10)),
                    __float2bfloat16(v11 - __bfloat162float(h11)));
            }
        }
    }
}

// ---------------------------------------------------------------------------
// Tensor-core causal flash attention (bf16 split, fp32-class accuracy).
// Block: 128 q rows x one (b,h). 256 thr, 8 warps x 16 rows.
// Key tiles of 64, double-buffered cp.async. Writes split bf16 attn out.
// ---------------------------------------------------------------------------
#define FSTRIDE 72
#define KVBUF 4608        // 64*72 elements per buffer
#define REGION 18432      // elements per stage (4 buffers)
#define FLASH_SMEM (2 * REGION * 2)   // 73728 bytes

__device__ __forceinline__ void load_kv(
    uint32_t sb, int region, int tid,
    const __nv_bfloat16* __restrict__ qh, const __nv_bfloat16* __restrict__ ql,
    int tokbase, int h)
{
    #pragma unroll
    for (int i = 0; i < 8; i++) {
        int idx = tid + i * 256;          // 0..2047
        int buf = idx >> 9;               // 0:Kh 1:Kl 2:Vh 3:Vl
        int within = idx & 511;
        int row = within >> 3, ch = within & 7;
        const __nv_bfloat16* base = (buf & 1) ? ql : qh;
        int coff = ((buf >> 1) + 1) * 1024 + h * 64;   // K:+1024, V:+2048
        const __nv_bfloat16* src = base + (size_t)(tokbase + row) * 3072 + coff + ch * 8;
        uint32_t dst = sb + (uint32_t)((region * REGION + buf * KVBUF + row * FSTRIDE + ch * 8) * 2);
        cpasync16(dst, src);
    }
}

__global__ __launch_bounds__(256)
void flash_tc(const __nv_bfloat16* __restrict__ qh, const __nv_bfloat16* __restrict__ ql,
              __nv_bfloat16* __restrict__ ath, __nv_bfloat16* __restrict__ atl)
{
    extern __shared__ __nv_bfloat16 fs[];
    const uint32_t sb = smem_u32(fs);
    const int tid = threadIdx.x, lane = tid & 31, w = tid >> 5;
    const int b = blockIdx.z, h = blockIdx.y, q0 = blockIdx.x * 128;
    const int g = lane >> 2, t = lane & 3;

    // ---- stage Q (region 1) + prefetch KV tile 0 (region 0) ----
    #pragma unroll
    for (int i = 0; i < 8; i++) {
        int idx = tid + i * 256;          // 0..2047
        int sp  = idx >> 10;              // 0 hi, 1 lo
        int within = idx & 1023;
        int row = within >> 3, ch = within & 7;
        const __nv_bfloat16* base = sp ? ql : qh;
        const __nv_bfloat16* src = base + (size_t)(b * T_LEN + q0 + row) * 3072 + h * 64 + ch * 8;
        uint32_t dst = sb + (uint32_t)((REGION + sp * 9216 + row * FSTRIDE + ch * 8) * 2);
        cpasync16(dst, src);
    }
    asm volatile("cp.async.commit_group;" ::: "memory");
    load_kv(sb, 0, tid, qh, ql, b * T_LEN, h);
    asm volatile("cp.async.commit_group;" ::: "memory");
    asm volatile("cp.async.wait_group 0;" ::: "memory");
    __syncthreads();

    // ---- Q fragments (kept in registers all kernel) ----
    uint32_t qa_h[4][4], qa_l[4][4];
    {
        int row = w * 16 + ((lane >> 3) & 1) * 8 + (lane & 7);
        int colh = (lane >> 4) * 8;
        #pragma unroll
        for (int ks = 0; ks < 4; ks++) {
            uint32_t addr = sb + (uint32_t)((REGION + row * FSTRIDE + ks * 16 + colh) * 2);
            ldmx4(qa_h[ks], addr);
            ldmx4(qa_l[ks], addr + 9216 * 2);
        }
    }
    __syncthreads();   // Q read complete; region 1 free

    const int nt_total = q0 / 64 + 2;
    if (nt_total > 1) {
        load_kv(sb, 1, tid, qh, ql, b * T_LEN + 64, h);
        asm volatile("cp.async.commit_group;" ::: "memory");
    }

    float oacc[8][4];
    #pragma unroll
    for (int j = 0; j < 8; j++)
        #pragma unroll
        for (int e = 0; e < 4; e++) oacc[j][e] = 0.f;
    float m[2] = {-3.0e38f, -3.0e38f};
    float l[2] = {0.f, 0.f};

    const float SC = 0.125f * 1.44269504089f;   // scale * log2(e)

    for (int kt = 0; kt < nt_total; kt++) {
        const int k0 = kt * 64;
        if (kt + 1 < nt_total) {
            load_kv(sb, (kt + 1) & 1, tid, qh, ql, b * T_LEN + (kt + 1) * 64, h);
            asm volatile("cp.async.commit_group;" ::: "memory");
            asm volatile("cp.async.wait_group 1;" ::: "memory");
        } else {
            asm volatile("cp.async.wait_group 0;" ::: "memory");
        }
        __syncthreads();

        const int rbase = q0 + w * 16 + g;          // rows rbase, rbase+8
        if (k0 <= rbase + 8) {                      // not fully masked for this warp
            const uint32_t rg = sb + (uint32_t)(((kt & 1) * REGION) * 2);
            const uint32_t sKh = rg, sKl = rg + KVBUF * 2;
            const uint32_t sVh = rg + 2 * KVBUF * 2, sVl = rg + 3 * KVBUF * 2;

            // ---- S = Q K^T (3-term split) ----
            float ps[8][4];
            #pragma unroll
            for (int j = 0; j < 8; j++)
                #pragma unroll
                for (int e = 0; e < 4; e++) ps[j][e] = 0.f;

            {
                int g8 = lane >> 3;
                int krow = 8 * (g8 >> 1) + (lane & 7);
                int kcol = (g8 & 1) * 8;
                #pragma unroll
                for (int ks = 0; ks < 4; ks++) {
                    uint32_t kbh[4][4], kbl[4][4];
                    #pragma unroll
                    for (int j2 = 0; j2 < 4; j2++) {
                        uint32_t off = (uint32_t)(((16 * j2 + krow) * FSTRIDE + 16 * ks + kcol) * 2);
                        ldmx4(kbh[j2], sKh + off);
                        ldmx4(kbl[j2], sKl + off);
                    }
                    #pragma unroll
                    for (int j = 0; j < 8; j++) {
                        const uint32_t* bhp = &kbh[j >> 1][(j & 1) * 2];
                        const uint32_t* blp = &kbl[j >> 1][(j & 1) * 2];
                        mma_bf16(ps[j], qa_h[ks], bhp);
                        mma_bf16(ps[j], qa_h[ks], blp);
                        mma_bf16(ps[j], qa_l[ks], bhp);
                    }
                }
            }

            // ---- scale + causal mask ----
            if (k0 + 63 > q0 + w * 16) {
                #pragma unroll
                for (int j = 0; j < 8; j++)
                    #pragma unroll
                    for (int e = 0; e < 4; e++) {
                        int col = k0 + j * 8 + t * 2 + (e & 1);
                        int row = rbase + (e >> 1) * 8;
                        ps[j][e] = (col <= row) ? ps[j][e] * SC : -1.0e30f;
                    }
            } else {
                #pragma unroll
                for (int j = 0; j < 8; j++)
                    #pragma unroll
                    for (int e = 0; e < 4; e++) ps[j][e] *= SC;
            }

            // ---- online softmax ----
            float tmax[2] = {-3.0e38f, -3.0e38f};
            #pragma unroll
            for (int j = 0; j < 8; j++) {
                tmax[0] = fmaxf(tmax[0], fmaxf(ps[j][0], ps[j][1]));
                tmax[1] = fmaxf(tmax[1], fmaxf(ps[j][2], ps[j][3]));
            }
            #pragma unroll
            for (int r = 0; r < 2; r++) {
                tmax[r] = fmaxf(tmax[r], __shfl_xor_sync(0xffffffffu, tmax[r], 1));
                tmax[r] = fmaxf(tmax[r], __shfl_xor_sync(0xffffffffu, tmax[r], 2));
            }
            float corr[2];
            #pragma unroll
            for (int r = 0; r < 2; r++) {
                float mn = fmaxf(m[r], tmax[r]);
                corr[r] = ex2(m[r] - mn);
                m[r] = mn;
            }
            float rsum[2] = {0.f, 0.f};
            #pragma unroll
            for (int j = 0; j < 8; j++)
                #pragma unroll
                for (int e = 0; e < 4; e++) {
                    float p = ex2(ps[j][e] - m[e >> 1]);
                    ps[j][e] = p;
                    rsum[e >> 1] += p;
                }
            #pragma unroll
            for (int r = 0; r < 2; r++) {
                rsum[r] += __shfl_xor_sync(0xffffffffu, rsum[r], 1);
                rsum[r] += __shfl_xor_sync(0xffffffffu, rsum[r], 2);
                l[r] = l[r] * corr[r] + rsum[r];
            }
            #pragma unroll
            for (int j = 0; j < 8; j++)
                #pragma unroll
                for (int e = 0; e < 4; e++) oacc[j][e] *= corr[e >> 1];

            // ---- O += P V (3-term split) ----
            {
                int g8 = lane >> 3;
                int vrow = (g8 & 1) * 8 + (lane & 7);
                int vcol = (g8 >> 1) * 8;
                #pragma unroll
                for (int ks = 0; ks < 4; ks++) {
                    // P a-fragments for this k-step from ps[2ks], ps[2ks+1]
                    uint32_t pah[4], pal[4];
                    #pragma unroll
                    for (int q2 = 0; q2 < 2; q2++) {      // q2: ntile 2ks+q2
                        const float* pv = ps[2 * ks + q2];
                        #pragma unroll
                        for (int rh = 0; rh < 2; rh++) {
                            float p0 = pv[rh * 2 + 0], p1 = pv[rh * 2 + 1];
                            __nv_bfloat16 h0 = __float2bfloat16(p0);
                            __nv_bfloat16 h1 = __float2bfloat16(p1);
                            pah[q2 * 2 + rh] = pk_bf(h0, h1);
                            pal[q2 * 2 + rh] = pk_bf(
                                __float2bfloat16(p0 - __bfloat162float(h0)),
                                __float2bfloat16(p1 - __bfloat162float(h1)));
                        }
                    }
                    uint32_t vbh[4][4], vbl[4][4];
                    #pragma unroll
                    for (int j2 = 0; j2 < 4; j2++) {
                        uint32_t off = (uint32_t)(((16 * ks + vrow) * FSTRIDE + 16 * j2 + vcol) * 2);
                        ldmx4t(vbh[j2], sVh + off);
                        ldmx4t(vbl[j2], sVl + off);
                    }
                    #pragma unroll
                    for (int dn = 0; dn < 8; dn++) {
                        const uint32_t* bhp = &vbh[dn >> 1][(dn & 1) * 2];
                        const uint32_t* blp = &vbl[dn >> 1][(dn & 1) * 2];
                        mma_bf16(oacc[dn], pah, bhp);
                        mma_bf16(oacc[dn], pah, blp);
                        mma_bf16(oacc[dn], pal, bhp);
                    }
                }
            }
        }
        __syncthreads();   // KV region free for next prefetch overwrite
    }

    // ---- epilogue: normalize, split bf16, store ----
    float inv[2] = {1.f / l[0], 1.f / l[1]};
    #pragma unroll
    for (int rh = 0; rh < 2; rh++) {
        int tok = b * T_LEN + q0 + w * 16 + g + rh * 8;
        #pragma unroll
        for (int j = 0; j < 8; j++) {
            int col = h * 64 + j * 8 + t * 2;
            float v0 = oacc[j][rh * 2 + 0] * inv[rh];
            float v1 = oacc[j][rh * 2 + 1] * inv[rh];
            __nv_bfloat16 h0 = __float2bfloat16(v0), h1 = __float2bfloat16(v1);
            *(uint32_t*)(ath + (size_t)tok * D_MODEL + col) = pk_bf(h0, h1);
            *(uint32_t*)(atl + (size_t)tok * D_MODEL + col) = pk_bf(
                __float2bfloat16(v0 - __bfloat162float(h0)),
                __float2bfloat16(v1 - __bfloat162float(h1)));
        }
    }
}

// ---------------------------------------------------------------------------
extern "C" void kernel_launch(void* const* d_in, const int* in_sizes, int n_in,
                              void* d_out, int out_size)
{
    const float *x = nullptr, *w_qkv = nullptr, *b_qkv = nullptr,
                *w_out = nullptr, *b_out = nullptr;
    for (int i = 0; i < n_in; i++) {
        switch (in_sizes[i]) {
            case 8388608: x     = (const float*)d_in[i]; break;
            case 3145728: w_qkv = (const float*)d_in[i]; break;
            case 3072:    b_qkv = (const float*)d_in[i]; break;
            case 1048576: w_out = (const float*)d_in[i]; break;
            case 1024:    b_out = (const float*)d_in[i]; break;
            default: break;
        }
    }
    float* out = (float*)d_out;

    __nv_bfloat16 *xh, *xl, *wqh, *wql, *woh, *wol, *qkvh, *qkvl, *ath, *atl;
    cudaGetSymbolAddress((void**)&xh, g_xh);   cudaGetSymbolAddress((void**)&xl, g_xl);
    cudaGetSymbolAddress((void**)&wqh, g_wqh); cudaGetSymbolAddress((void**)&wql, g_wql);
    cudaGetSymbolAddress((void**)&woh, g_woh); cudaGetSymbolAddress((void**)&wol, g_wol);
    cudaGetSymbolAddress((void**)&qkvh, g_qkvh); cudaGetSymbolAddress((void**)&qkvl, g_qkvl);
    cudaGetSymbolAddress((void**)&ath, g_ath); cudaGetSymbolAddress((void**)&atl, g_atl);

    const int SMEM = STG_E * 2 * 2 * 2;   // 81920
    cudaFuncSetAttribute(gemm_bf16split<0>, cudaFuncAttributeMaxDynamicSharedMemorySize, SMEM);
    cudaFuncSetAttribute(gemm_bf16split<1>, cudaFuncAttributeMaxDynamicSharedMemorySize, SMEM);
    cudaFuncSetAttribute(flash_tc, cudaFuncAttributeMaxDynamicSharedMemorySize, FLASH_SMEM);

    // 0) pre-split inputs
    int n4x = TOKENS * D_MODEL / 4;
    split_bf16<<<(n4x + 255) / 256, 256>>>(x, xh, xl, n4x);
    int n4q = 3 * D_MODEL * D_MODEL / 4;
    split_bf16<<<(n4q + 255) / 256, 256>>>(w_qkv, wqh, wql, n4q);
    int n4o = D_MODEL * D_MODEL / 4;
    split_bf16<<<(n4o + 255) / 256, 256>>>(w_out, woh, wol, n4o);

    // 1) QKV projection -> split bf16 qkv
    gemm_bf16split<1><<<dim3(3 * D_MODEL / 128, TOKENS / 128), 256, SMEM>>>(
        xh, xl, wqh, wql, b_qkv, nullptr, qkvh, qkvl, TOKENS, 3 * D_MODEL, D_MODEL);

    // 2) TC causal flash attention -> split bf16 attn
    flash_tc<<<dim3(T_LEN / 128, N_HEADS, B_SIZE), 256, FLASH_SMEM>>>(qkvh, qkvl, ath, atl);

    // 3) Output projection -> fp32 d_out
    gemm_bf16split<0><<<dim3(D_MODEL / 128, TOKENS / 128), 256, SMEM>>>(
        ath, atl, woh, wol, b_out, out, nullptr, nullptr, TOKENS, D_MODEL, D_MODEL);
}

// round 11
// speedup vs baseline: 4.0410x; 1.0166x over previous
#include <cuda_runtime.h>
#include <cuda_bf16.h>
#include <math.h>
#include <stdint.h>

#define D_MODEL 1024
#define N_HEADS 16
#define HEAD_DIM 64
#define B_SIZE 4
#define T_LEN 2048
#define TOKENS (B_SIZE * T_LEN)   // 8192

// ---------------- scratch (device globals; allocation-free) ----------------
__device__ __nv_bfloat16 g_xh[(size_t)TOKENS * D_MODEL], g_xl[(size_t)TOKENS * D_MODEL];
__device__ __nv_bfloat16 g_wqh[(size_t)3 * D_MODEL * D_MODEL], g_wql[(size_t)3 * D_MODEL * D_MODEL];
__device__ __nv_bfloat16 g_woh[(size_t)D_MODEL * D_MODEL], g_wol[(size_t)D_MODEL * D_MODEL];
__device__ __nv_bfloat16 g_qkvh[(size_t)TOKENS * 3 * D_MODEL], g_qkvl[(size_t)TOKENS * 3 * D_MODEL];
__device__ __nv_bfloat16 g_ath[(size_t)TOKENS * D_MODEL], g_atl[(size_t)TOKENS * D_MODEL];

// ---------------------------- small helpers --------------------------------
__device__ __forceinline__ uint32_t smem_u32(const void* p) {
    uint32_t a;
    asm("{ .reg .u64 t; cvta.to.shared.u64 t, %1; cvt.u32.u64 %0, t; }"
        : "=r"(a) : "l"(p));
    return a;
}
__device__ __forceinline__ uint32_t pk_bf(__nv_bfloat16 a, __nv_bfloat16 b) {
    return (uint32_t)__bfloat16_as_ushort(a) | ((uint32_t)__bfloat16_as_ushort(b) << 16);
}
__device__ __forceinline__ void mma_bf16(float* c, const uint32_t* a, const uint32_t* b) {
    asm volatile(
        "mma.sync.aligned.m16n8k16.row.col.f32.bf16.bf16.f32 "
        "{%0,%1,%2,%3}, {%4,%5,%6,%7}, {%8,%9}, {%0,%1,%2,%3};"
        : "+f"(c[0]), "+f"(c[1]), "+f"(c[2]), "+f"(c[3])
        : "r"(a[0]), "r"(a[1]), "r"(a[2]), "r"(a[3]), "r"(b[0]), "r"(b[1]));
}
__device__ __forceinline__ void ldmx4(uint32_t r[4], uint32_t addr) {
    asm volatile("ldmatrix.sync.aligned.m8n8.x4.shared.b16 {%0,%1,%2,%3}, [%4];"
        : "=r"(r[0]), "=r"(r[1]), "=r"(r[2]), "=r"(r[3]) : "r"(addr));
}
__device__ __forceinline__ void ldmx4t(uint32_t r[4], uint32_t addr) {
    asm volatile("ldmatrix.sync.aligned.m8n8.x4.trans.shared.b16 {%0,%1,%2,%3}, [%4];"
        : "=r"(r[0]), "=r"(r[1]), "=r"(r[2]), "=r"(r[3]) : "r"(addr));
}
__device__ __forceinline__ void cpasync16(uint32_t dst, const void* src) {
    asm volatile("cp.async.cg.shared.global [%0], [%1], 16;" :: "r"(dst), "l"(src) : "memory");
}
__device__ __forceinline__ float ex2(float x) {
    float y; asm("ex2.approx.f32 %0, %1;" : "=f"(y) : "f"(x)); return y;
}

// -------------------- pre-split: fp32 -> bf16 hi + lo ----------------------
__global__ __launch_bounds__(256)
void split_bf16(const float* __restrict__ src, __nv_bfloat16* __restrict__ hi,
                __nv_bfloat16* __restrict__ lo, int n4)
{
    int i = blockIdx.x * 256 + threadIdx.x;
    if (i >= n4) return;
    float4 f = ((const float4*)src)[i];
    float v[4] = {f.x, f.y, f.z, f.w};
    __nv_bfloat16 h[4], l[4];
    #pragma unroll
    for (int j = 0; j < 4; j++) {
        h[j] = __float2bfloat16(v[j]);
        l[j] = __float2bfloat16(v[j] - __bfloat162float(h[j]));
    }
    ((uint2*)hi)[i] = make_uint2(pk_bf(h[0], h[1]), pk_bf(h[2], h[3]));
    ((uint2*)lo)[i] = make_uint2(pk_bf(l[0], l[1]), pk_bf(l[2], l[3]));
}

// ---------------------------------------------------------------------------
// bf16 split GEMM: C[M,N] = A@W^T + bias. OM=0: fp32 out; OM=1: bf16 hi/lo out.
// Split passes issued pass-major: 16 independent accumulators between reuse.
// ---------------------------------------------------------------------------
#define STG_E 20480
#define BUF_E 5120

__device__ __forceinline__ void stage_load(
    uint32_t sb, int s, int tid,
    const __nv_bfloat16* __restrict__ Ah_g, const __nv_bfloat16* __restrict__ Al_g,
    const __nv_bfloat16* __restrict__ Bh_g, const __nv_bfloat16* __restrict__ Bl_g,
    int brow, int bcol, int K, int k0)
{
    #pragma unroll
    for (int i = 0; i < 8; i++) {
        int c      = tid + i * 256;
        int buf    = c >> 9;
        int within = c & 511;
        int row    = within >> 2;
        int ch     = within & 3;
        const __nv_bfloat16* g = (buf == 0) ? Ah_g : (buf == 1) ? Al_g
                               : (buf == 2) ? Bh_g : Bl_g;
        int gr = ((buf < 2) ? brow : bcol) + row;
        const __nv_bfloat16* src = g + (size_t)gr * K + k0 + ch * 8;
        uint32_t dst = sb + (uint32_t)((s * STG_E + buf * BUF_E + row * 40 + ch * 8) * 2);
        cpasync16(dst, src);
    }
}

template<int OM>
__global__ __launch_bounds__(256, 2)
void gemm_bf16split(const __nv_bfloat16* __restrict__ Ah_g, const __nv_bfloat16* __restrict__ Al_g,
                    const __nv_bfloat16* __restrict__ Bh_g, const __nv_bfloat16* __restrict__ Bl_g,
                    const float* __restrict__ bias, float* __restrict__ C,
                    __nv_bfloat16* __restrict__ Ch, __nv_bfloat16* __restrict__ Cl,
                    int M, int N, int K)
{
    extern __shared__ __nv_bfloat16 sm[];
    const uint32_t sb   = smem_u32(sm);
    const int tid  = threadIdx.x;
    const int lane = tid & 31;
    const int w    = tid >> 5;
    const int wm   = w >> 2;
    const int wn   = w & 3;
    const int sub  = lane & 7;
    const int matid = lane >> 3;
    const int brow = blockIdx.y * 128;
    const int bcol = blockIdx.x * 128;

    float acc[4][4][4];
    #pragma unroll
    for (int i = 0; i < 4; i++)
        #pragma unroll
        for (int j = 0; j < 4; j++)
            #pragma unroll
            for (int e = 0; e < 4; e++) acc[i][j][e] = 0.f;

    const int arow = wm * 64 + ((matid & 1) << 3) + sub;
    const int acolb = ((matid >> 1) << 3);
    const int nrow = wn * 32 + ((matid >> 1) << 3) + sub;
    const int ncolb = ((matid & 1) << 3);

    const int NC = K >> 5;

    stage_load(sb, 0, tid, Ah_g, Al_g, Bh_g, Bl_g, brow, bcol, K, 0);
    asm volatile("cp.async.commit_group;" ::: "memory");

    for (int kc = 0; kc < NC; kc++) {
        asm volatile("cp.async.wait_group 0;" ::: "memory");
        __syncthreads();

        if (kc + 1 < NC) {
            stage_load(sb, (kc + 1) & 1, tid, Ah_g, Al_g, Bh_g, Bl_g,
                       brow, bcol, K, (kc + 1) * 32);
            asm volatile("cp.async.commit_group;" ::: "memory");
        }

        const int s = kc & 1;
        const uint32_t sAh = sb + (uint32_t)((s * STG_E) * 2);
        const uint32_t sAl = sAh + BUF_E * 2;
        const uint32_t sBh = sAl + BUF_E * 2;
        const uint32_t sBl = sBh + BUF_E * 2;

        #pragma unroll
        for (int ks = 0; ks < 32; ks += 16) {
            uint32_t ah[4][4], al[4][4], bh[2][4], bl[2][4];
            #pragma unroll
            for (int mt = 0; mt < 4; mt++) {
                uint32_t off = (uint32_t)(((arow + mt * 16) * 40 + ks + acolb) * 2);
                ldmx4(ah[mt], sAh + off);
                ldmx4(al[mt], sAl + off);
            }
            #pragma unroll
            for (int ng = 0; ng < 2; ng++) {
                uint32_t off = (uint32_t)(((nrow + ng * 16) * 40 + ks + ncolb) * 2);
                ldmx4(bh[ng], sBh + off);
                ldmx4(bl[ng], sBl + off);
            }
            // pass-major issue: 16 independent accumulators between same-acc reuse
            #pragma unroll
            for (int sp = 0; sp < 3; sp++) {
                #pragma unroll
                for (int mt = 0; mt < 4; mt++)
                    #pragma unroll
                    for (int nt = 0; nt < 4; nt++) {
                        const uint32_t* ap = (sp == 2) ? al[mt] : ah[mt];
                        const uint32_t* bp = (sp == 1)
                            ? &bl[nt >> 1][(nt & 1) * 2]
                            : &bh[nt >> 1][(nt & 1) * 2];
                        mma_bf16(acc[mt][nt], ap, bp);
                    }
            }
        }
        __syncthreads();
    }

    const int rg = lane >> 2;
    const int ct = lane & 3;
    #pragma unroll
    for (int mt = 0; mt < 4; mt++) {
        int r0 = brow + wm * 64 + mt * 16 + rg;
        #pragma unroll
        for (int nt = 0; nt < 4; nt++) {
            int c0 = bcol + wn * 32 + nt * 8 + ct * 2;
            float b0 = bias[c0], b1 = bias[c0 + 1];
            float v00 = acc[mt][nt][0] + b0, v01 = acc[mt][nt][1] + b1;
            float v10 = acc[mt][nt][2] + b0, v11 = acc[mt][nt][3] + b1;
            if (OM == 0) {
                *(float2*)(C + (size_t)r0 * N + c0) = make_float2(v00, v01);
                *(float2*)(C + (size_t)(r0 + 8) * N + c0) = make_float2(v10, v11);
            } else {
                __nv_bfloat16 h00 = __float2bfloat16(v00), h01 = __float2bfloat16(v01);
                __nv_bfloat16 h10 = __float2bfloat16(v10), h11 = __float2bfloat16(v11);
                *(uint32_t*)(Ch + (size_t)r0 * N + c0) = pk_bf(h00, h01);
                *(uint32_t*)(Ch + (size_t)(r0 + 8) * N + c0) = pk_bf(h10, h11);
                *(uint32_t*)(Cl + (size_t)r0 * N + c0) = pk_bf(
                    __float2bfloat16(v00 - __bfloat162float(h00)),
                    __float2bfloat16(v01 - __bfloat162float(h01)));
                *(uint32_t*)(Cl + (size_t)(r0 + 8) * N + c0) = pk_bf(
                    __float2bfloat16(v10 - __bfloat162float(h10)),
                    __float2bfloat16(v11 - __bfloat162float(h11)));
            }
        }
    }
}

// ---------------------------------------------------------------------------
// Tensor-core causal flash attention (bf16 split, fp32-class accuracy).
// ---------------------------------------------------------------------------
#define FSTRIDE 72
#define KVBUF 4608
#define REGION 18432
#define FLASH_SMEM (2 * REGION * 2)   // 73728 bytes

__device__ __forceinline__ void load_kv(
    uint32_t sb, int region, int tid,
    const __nv_bfloat16* __restrict__ qh, const __nv_bfloat16* __restrict__ ql,
    int tokbase, int h)
{
    #pragma unroll
    for (int i = 0; i < 8; i++) {
        int idx = tid + i * 256;
        int buf = idx >> 9;
        int within = idx & 511;
        int row = within >> 3, ch = within & 7;
        const __nv_bfloat16* base = (buf & 1) ? ql : qh;
        int coff = ((buf >> 1) + 1) * 1024 + h * 64;
        const __nv_bfloat16* src = base + (size_t)(tokbase + row) * 3072 + coff + ch * 8;
        uint32_t dst = sb + (uint32_t)((region * REGION + buf * KVBUF + row * FSTRIDE + ch * 8) * 2);
        cpasync16(dst, src);
    }
}

__global__ __launch_bounds__(256)
void flash_tc(const __nv_bfloat16* __restrict__ qh, const __nv_bfloat16* __restrict__ ql,
              __nv_bfloat16* __restrict__ ath, __nv_bfloat16* __restrict__ atl)
{
    extern __shared__ __nv_bfloat16 fs[];
    const uint32_t sb = smem_u32(fs);
    const int tid = threadIdx.x, lane = tid & 31, w = tid >> 5;
    const int b = blockIdx.z, h = blockIdx.y, q0 = blockIdx.x * 128;
    const int g = lane >> 2, t = lane & 3;

    #pragma unroll
    for (int i = 0; i < 8; i++) {
        int idx = tid + i * 256;
        int sp  = idx >> 10;
        int within = idx & 1023;
        int row = within >> 3, ch = within & 7;
        const __nv_bfloat16* base = sp ? ql : qh;
        const __nv_bfloat16* src = base + (size_t)(b * T_LEN + q0 + row) * 3072 + h * 64 + ch * 8;
        uint32_t dst = sb + (uint32_t)((REGION + sp * 9216 + row * FSTRIDE + ch * 8) * 2);
        cpasync16(dst, src);
    }
    asm volatile("cp.async.commit_group;" ::: "memory");
    load_kv(sb, 0, tid, qh, ql, b * T_LEN, h);
    asm volatile("cp.async.commit_group;" ::: "memory");
    asm volatile("cp.async.wait_group 0;" ::: "memory");
    __syncthreads();

    uint32_t qa_h[4][4], qa_l[4][4];
    {
        int row = w * 16 + ((lane >> 3) & 1) * 8 + (lane & 7);
        int colh = (lane >> 4) * 8;
        #pragma unroll
        for (int ks = 0; ks < 4; ks++) {
            uint32_t addr = sb + (uint32_t)((REGION + row * FSTRIDE + ks * 16 + colh) * 2);
            ldmx4(qa_h[ks], addr);
            ldmx4(qa_l[ks], addr + 9216 * 2);
        }
    }
    __syncthreads();

    const int nt_total = q0 / 64 + 2;
    if (nt_total > 1) {
        load_kv(sb, 1, tid, qh, ql, b * T_LEN + 64, h);
        asm volatile("cp.async.commit_group;" ::: "memory");
    }

    float oacc[8][4];
    #pragma unroll
    for (int j = 0; j < 8; j++)
        #pragma unroll
        for (int e = 0; e < 4; e++) oacc[j][e] = 0.f;
    float m[2] = {-3.0e38f, -3.0e38f};
    float l[2] = {0.f, 0.f};

    const float SC = 0.125f * 1.44269504089f;

    for (int kt = 0; kt < nt_total; kt++) {
        const int k0 = kt * 64;
        if (kt + 1 < nt_total) {
            load_kv(sb, (kt + 1) & 1, tid, qh, ql, b * T_LEN + (kt + 1) * 64, h);
            asm volatile("cp.async.commit_group;" ::: "memory");
            asm volatile("cp.async.wait_group 1;" ::: "memory");
        } else {
            asm volatile("cp.async.wait_group 0;" ::: "memory");
        }
        __syncthreads();

        const int rbase = q0 + w * 16 + g;
        if (k0 <= rbase + 8) {
            const uint32_t rg2 = sb + (uint32_t)(((kt & 1) * REGION) * 2);
            const uint32_t sKh = rg2, sKl = rg2 + KVBUF * 2;
            const uint32_t sVh = rg2 + 2 * KVBUF * 2, sVl = rg2 + 3 * KVBUF * 2;

            // ---- S = Q K^T (3-term split, pass-major for ILP) ----
            float ps[8][4];
            #pragma unroll
            for (int j = 0; j < 8; j++)
                #pragma unroll
                for (int e = 0; e < 4; e++) ps[j][e] = 0.f;

            {
                int g8 = lane >> 3;
                int krow = 8 * (g8 >> 1) + (lane & 7);
                int kcol = (g8 & 1) * 8;
                #pragma unroll
                for (int ks = 0; ks < 4; ks++) {
                    uint32_t kbh[4][4], kbl[4][4];
                    #pragma unroll
                    for (int j2 = 0; j2 < 4; j2++) {
                        uint32_t off = (uint32_t)(((16 * j2 + krow) * FSTRIDE + 16 * ks + kcol) * 2);
                        ldmx4(kbh[j2], sKh + off);
                        ldmx4(kbl[j2], sKl + off);
                    }
                    #pragma unroll
                    for (int sp = 0; sp < 3; sp++) {
                        const uint32_t* qa = (sp == 2) ? qa_l[ks] : qa_h[ks];
                        #pragma unroll
                        for (int j = 0; j < 8; j++) {
                            const uint32_t* bp = (sp == 1)
                                ? &kbl[j >> 1][(j & 1) * 2]
                                : &kbh[j >> 1][(j & 1) * 2];
                            mma_bf16(ps[j], qa, bp);
                        }
                    }
                }
            }

            // ---- scale + causal mask ----
            if (k0 + 63 > q0 + w * 16) {
                #pragma unroll
                for (int j = 0; j < 8; j++)
                    #pragma unroll
                    for (int e = 0; e < 4; e++) {
                        int col = k0 + j * 8 + t * 2 + (e & 1);
                        int row = rbase + (e >> 1) * 8;
                        ps[j][e] = (col <= row) ? ps[j][e] * SC : -1.0e30f;
                    }
            } else {
                #pragma unroll
                for (int j = 0; j < 8; j++)
                    #pragma unroll
                    for (int e = 0; e < 4; e++) ps[j][e] *= SC;
            }

            // ---- online softmax ----
            float tmax[2] = {-3.0e38f, -3.0e38f};
            #pragma unroll
            for (int j = 0; j < 8; j++) {
                tmax[0] = fmaxf(tmax[0], fmaxf(ps[j][0], ps[j][1]));
                tmax[1] = fmaxf(tmax[1], fmaxf(ps[j][2], ps[j][3]));
            }
            #pragma unroll
            for (int r = 0; r < 2; r++) {
                tmax[r] = fmaxf(tmax[r], __shfl_xor_sync(0xffffffffu, tmax[r], 1));
                tmax[r] = fmaxf(tmax[r], __shfl_xor_sync(0xffffffffu, tmax[r], 2));
            }
            float corr[2];
            #pragma unroll
            for (int r = 0; r < 2; r++) {
                float mn = fmaxf(m[r], tmax[r]);
                corr[r] = ex2(m[r] - mn);
                m[r] = mn;
            }
            float rsum[2] = {0.f, 0.f};
            #pragma unroll
            for (int j = 0; j < 8; j++)
                #pragma unroll
                for (int e = 0; e < 4; e++) {
                    float p = ex2(ps[j][e] - m[e >> 1]);
                    ps[j][e] = p;
                    rsum[e >> 1] += p;
                }
            #pragma unroll
            for (int r = 0; r < 2; r++) {
                rsum[r] += __shfl_xor_sync(0xffffffffu, rsum[r], 1);
                rsum[r] += __shfl_xor_sync(0xffffffffu, rsum[r], 2);
                l[r] = l[r] * corr[r] + rsum[r];
            }
            #pragma unroll
            for (int j = 0; j < 8; j++)
                #pragma unroll
                for (int e = 0; e < 4; e++) oacc[j][e] *= corr[e >> 1];

            // ---- O += P V (3-term split, pass-major for ILP) ----
            {
                int g8 = lane >> 3;
                int vrow = (g8 & 1) * 8 + (lane & 7);
                int vcol = (g8 >> 1) * 8;
                #pragma unroll
                for (int ks = 0; ks < 4; ks++) {
                    uint32_t pah[4], pal[4];
                    #pragma unroll
                    for (int q2 = 0; q2 < 2; q2++) {
                        const float* pv = ps[2 * ks + q2];
                        #pragma unroll
                        for (int rh = 0; rh < 2; rh++) {
                            float p0 = pv[rh * 2 + 0], p1 = pv[rh * 2 + 1];
                            __nv_bfloat16 h0 = __float2bfloat16(p0);
                            __nv_bfloat16 h1 = __float2bfloat16(p1);
                            pah[q2 * 2 + rh] = pk_bf(h0, h1);
                            pal[q2 * 2 + rh] = pk_bf(
                                __float2bfloat16(p0 - __bfloat162float(h0)),
                                __float2bfloat16(p1 - __bfloat162float(h1)));
                        }
                    }
                    uint32_t vbh[4][4], vbl[4][4];
                    #pragma unroll
                    for (int j2 = 0; j2 < 4; j2++) {
                        uint32_t off = (uint32_t)(((16 * ks + vrow) * FSTRIDE + 16 * j2 + vcol) * 2);
                        ldmx4t(vbh[j2], sVh + off);
                        ldmx4t(vbl[j2], sVl + off);
                    }
                    #pragma unroll
                    for (int sp = 0; sp < 3; sp++) {
                        const uint32_t* pa = (sp == 2) ? pal : pah;
                        #pragma unroll
                        for (int dn = 0; dn < 8; dn++) {
                            const uint32_t* bp = (sp == 1)
                                ? &vbl[dn >> 1][(dn & 1) * 2]
                                : &vbh[dn >> 1][(dn & 1) * 2];
                            mma_bf16(oacc[dn], pa, bp);
                        }
                    }
                }
            }
        }
        __syncthreads();
    }

    // ---- epilogue: normalize, split bf16, store ----
    float inv[2] = {1.f / l[0], 1.f / l[1]};
    #pragma unroll
    for (int rh = 0; rh < 2; rh++) {
        int tok = b * T_LEN + q0 + w * 16 + g + rh * 8;
        #pragma unroll
        for (int j = 0; j < 8; j++) {
            int col = h * 64 + j * 8 + t * 2;
            float v0 = oacc[j][rh * 2 + 0] * inv[rh];
            float v1 = oacc[j][rh * 2 + 1] * inv[rh];
            __nv_bfloat16 h0 = __float2bfloat16(v0), h1 = __float2bfloat16(v1);
            *(uint32_t*)(ath + (size_t)tok * D_MODEL + col) = pk_bf(h0, h1);
            *(uint32_t*)(atl + (size_t)tok * D_MODEL + col) = pk_bf(
                __float2bfloat16(v0 - __bfloat162float(h0)),
                __float2bfloat16(v1 - __bfloat162float(h1)));
        }
    }
}

// ---------------------------------------------------------------------------
extern "C" void kernel_launch(void* const* d_in, const int* in_sizes, int n_in,
                              void* d_out, int out_size)
{
    const float *x = nullptr, *w_qkv = nullptr, *b_qkv = nullptr,
                *w_out = nullptr, *b_out = nullptr;
    for (int i = 0; i < n_in; i++) {
        switch (in_sizes[i]) {
            case 8388608: x     = (const float*)d_in[i]; break;
            case 3145728: w_qkv = (const float*)d_in[i]; break;
            case 3072:    b_qkv = (const float*)d_in[i]; break;
            case 1048576: w_out = (const float*)d_in[i]; break;
            case 1024:    b_out = (const float*)d_in[i]; break;
            default: break;
        }
    }
    float* out = (float*)d_out;

    __nv_bfloat16 *xh, *xl, *wqh, *wql, *woh, *wol, *qkvh, *qkvl, *ath, *atl;
    cudaGetSymbolAddress((void**)&xh, g_xh);   cudaGetSymbolAddress((void**)&xl, g_xl);
    cudaGetSymbolAddress((void**)&wqh, g_wqh); cudaGetSymbolAddress((void**)&wql, g_wql);
    cudaGetSymbolAddress((void**)&woh, g_woh); cudaGetSymbolAddress((void**)&wol, g_wol);
    cudaGetSymbolAddress((void**)&qkvh, g_qkvh); cudaGetSymbolAddress((void**)&qkvl, g_qkvl);
    cudaGetSymbolAddress((void**)&ath, g_ath); cudaGetSymbolAddress((void**)&atl, g_atl);

    const int SMEM = STG_E * 2 * 2 * 2;   // 81920
    cudaFuncSetAttribute(gemm_bf16split<0>, cudaFuncAttributeMaxDynamicSharedMemorySize, SMEM);
    cudaFuncSetAttribute(gemm_bf16split<1>, cudaFuncAttributeMaxDynamicSharedMemorySize, SMEM);
    cudaFuncSetAttribute(flash_tc, cudaFuncAttributeMaxDynamicSharedMemorySize, FLASH_SMEM);

    // 0) pre-split inputs
    int n4x = TOKENS * D_MODEL / 4;
    split_bf16<<<(n4x + 255) / 256, 256>>>(x, xh, xl, n4x);
    int n4q = 3 * D_MODEL * D_MODEL / 4;
    split_bf16<<<(n4q + 255) / 256, 256>>>(w_qkv, wqh, wql, n4q);
    int n4o = D_MODEL * D_MODEL / 4;
    split_bf16<<<(n4o + 255) / 256, 256>>>(w_out, woh, wol, n4o);

    // 1) QKV projection -> split bf16 qkv
    gemm_bf16split<1><<<dim3(3 * D_MODEL / 128, TOKENS / 128), 256, SMEM>>>(
        xh, xl, wqh, wql, b_qkv, nullptr, qkvh, qkvl, TOKENS, 3 * D_MODEL, D_MODEL);

    // 2) TC causal flash attention -> split bf16 attn
    flash_tc<<<dim3(T_LEN / 128, N_HEADS, B_SIZE), 256, FLASH_SMEM>>>(qkvh, qkvl, ath, atl);

    // 3) Output projection -> fp32 d_out
    gemm_bf16split<0><<<dim3(D_MODEL / 128, TOKENS / 128), 256, SMEM>>>(
        ath, atl, woh, wol, b_out, out, nullptr, nullptr, TOKENS, D_MODEL, D_MODEL);
}

// round 13
// speedup vs baseline: 4.3239x; 1.0700x over previous
#include <cuda_runtime.h>
#include <cuda_bf16.h>
#include <math.h>
#include <stdint.h>

#define D_MODEL 1024
#define N_HEADS 16
#define HEAD_DIM 64
#define B_SIZE 4
#define T_LEN 2048
#define TOKENS (B_SIZE * T_LEN)   // 8192

// ---------------- scratch (device globals; allocation-free) ----------------
__device__ __nv_bfloat16 g_xh[(size_t)TOKENS * D_MODEL], g_xl[(size_t)TOKENS * D_MODEL];
__device__ __nv_bfloat16 g_wqh[(size_t)3 * D_MODEL * D_MODEL], g_wql[(size_t)3 * D_MODEL * D_MODEL];
__device__ __nv_bfloat16 g_woh[(size_t)D_MODEL * D_MODEL], g_wol[(size_t)D_MODEL * D_MODEL];
__device__ __nv_bfloat16 g_qkvh[(size_t)TOKENS * 3 * D_MODEL], g_qkvl[(size_t)TOKENS * 3 * D_MODEL];
__device__ __nv_bfloat16 g_ath[(size_t)TOKENS * D_MODEL], g_atl[(size_t)TOKENS * D_MODEL];

// ---------------------------- small helpers --------------------------------
__device__ __forceinline__ uint32_t smem_u32(const void* p) {
    uint32_t a;
    asm("{ .reg .u64 t; cvta.to.shared.u64 t, %1; cvt.u32.u64 %0, t; }"
        : "=r"(a) : "l"(p));
    return a;
}
__device__ __forceinline__ uint32_t pk_bf(__nv_bfloat16 a, __nv_bfloat16 b) {
    return (uint32_t)__bfloat16_as_ushort(a) | ((uint32_t)__bfloat16_as_ushort(b) << 16);
}
__device__ __forceinline__ void mma_bf16(float* c, const uint32_t* a, const uint32_t* b) {
    asm volatile(
        "mma.sync.aligned.m16n8k16.row.col.f32.bf16.bf16.f32 "
        "{%0,%1,%2,%3}, {%4,%5,%6,%7}, {%8,%9}, {%0,%1,%2,%3};"
        : "+f"(c[0]), "+f"(c[1]), "+f"(c[2]), "+f"(c[3])
        : "r"(a[0]), "r"(a[1]), "r"(a[2]), "r"(a[3]), "r"(b[0]), "r"(b[1]));
}
__device__ __forceinline__ void ldmx4(uint32_t r[4], uint32_t addr) {
    asm volatile("ldmatrix.sync.aligned.m8n8.x4.shared.b16 {%0,%1,%2,%3}, [%4];"
        : "=r"(r[0]), "=r"(r[1]), "=r"(r[2]), "=r"(r[3]) : "r"(addr));
}
__device__ __forceinline__ void ldmx4t(uint32_t r[4], uint32_t addr) {
    asm volatile("ldmatrix.sync.aligned.m8n8.x4.trans.shared.b16 {%0,%1,%2,%3}, [%4];"
        : "=r"(r[0]), "=r"(r[1]), "=r"(r[2]), "=r"(r[3]) : "r"(addr));
}
__device__ __forceinline__ void cpasync16(uint32_t dst, const void* src) {
    asm volatile("cp.async.cg.shared.global [%0], [%1], 16;" :: "r"(dst), "l"(src) : "memory");
}
__device__ __forceinline__ float ex2(float x) {
    float y; asm("ex2.approx.f32 %0, %1;" : "=f"(y) : "f"(x)); return y;
}

// -------------------- pre-split: fp32 -> bf16 hi + lo ----------------------
__global__ __launch_bounds__(256)
void split_bf16(const float* __restrict__ src, __nv_bfloat16* __restrict__ hi,
                __nv_bfloat16* __restrict__ lo, int n4)
{
    int i = blockIdx.x * 256 + threadIdx.x;
    if (i >= n4) return;
    float4 f = ((const float4*)src)[i];
    float v[4] = {f.x, f.y, f.z, f.w};
    __nv_bfloat16 h[4], l[4];
    #pragma unroll
    for (int j = 0; j < 4; j++) {
        h[j] = __float2bfloat16(v[j]);
        l[j] = __float2bfloat16(v[j] - __bfloat162float(h[j]));
    }
    ((uint2*)hi)[i] = make_uint2(pk_bf(h[0], h[1]), pk_bf(h[2], h[3]));
    ((uint2*)lo)[i] = make_uint2(pk_bf(l[0], l[1]), pk_bf(l[2], l[3]));
}

// ---------------------------------------------------------------------------
// bf16 split GEMM v2: 512 threads (16 warps 4x4, warp tile 32x32), BK=64,
// 2-stage cp.async, stride-72 smem rows (ldmatrix conflict-free).
// C[M,N] = A@W^T + bias. OM=0: fp32 out; OM=1: bf16 hi/lo out.
// ---------------------------------------------------------------------------
#define GSTRIDE 72
#define BUF_E (128 * GSTRIDE)      // 9216 el per buffer
#define STG_E (4 * BUF_E)          // 36864 el per stage
#define GEMM_SMEM (2 * STG_E * 2)  // 147456 bytes

__device__ __forceinline__ void stage_load(
    uint32_t sb, int s, int tid,
    const __nv_bfloat16* __restrict__ Ah_g, const __nv_bfloat16* __restrict__ Al_g,
    const __nv_bfloat16* __restrict__ Bh_g, const __nv_bfloat16* __restrict__ Bl_g,
    int brow, int bcol, int K, int k0)
{
    // 4 buffers * 128 rows * 8 chunks = 4096 16B chunks; 512 thr * 8 iters
    #pragma unroll
    for (int i = 0; i < 8; i++) {
        int c      = tid + i * 512;      // 0..4095
        int buf    = c >> 10;            // 0:Ah 1:Al 2:Bh 3:Bl
        int within = c & 1023;
        int row    = within >> 3;        // 0..127
        int ch     = within & 7;         // 0..7 (8 el each)
        const __nv_bfloat16* g = (buf == 0) ? Ah_g : (buf == 1) ? Al_g
                               : (buf == 2) ? Bh_g : Bl_g;
        int gr = ((buf < 2) ? brow : bcol) + row;
        const __nv_bfloat16* src = g + (size_t)gr * K + k0 + ch * 8;
        uint32_t dst = sb + (uint32_t)((s * STG_E + buf * BUF_E + row * GSTRIDE + ch * 8) * 2);
        cpasync16(dst, src);
    }
}

template<int OM>
__global__ __launch_bounds__(512, 1)
void gemm_bf16split(const __nv_bfloat16* __restrict__ Ah_g, const __nv_bfloat16* __restrict__ Al_g,
                    const __nv_bfloat16* __restrict__ Bh_g, const __nv_bfloat16* __restrict__ Bl_g,
                    const float* __restrict__ bias, float* __restrict__ C,
                    __nv_bfloat16* __restrict__ Ch, __nv_bfloat16* __restrict__ Cl,
                    int M, int N, int K)
{
    extern __shared__ __nv_bfloat16 sm[];
    const uint32_t sb   = smem_u32(sm);
    const int tid  = threadIdx.x;
    const int lane = tid & 31;
    const int w    = tid >> 5;          // 0..15
    const int wm   = w >> 2;            // 0..3 (32-row band)
    const int wn   = w & 3;             // 0..3 (32-col band)
    const int sub  = lane & 7;
    const int matid = lane >> 3;
    const int brow = blockIdx.y * 128;
    const int bcol = blockIdx.x * 128;

    float acc[2][4][4];
    #pragma unroll
    for (int i = 0; i < 2; i++)
        #pragma unroll
        for (int j = 0; j < 4; j++)
            #pragma unroll
            for (int e = 0; e < 4; e++) acc[i][j][e] = 0.f;

    const int arow = wm * 32 + ((matid & 1) << 3) + sub;   // + mt*16
    const int acolb = ((matid >> 1) << 3);                 // + ks
    const int nrow = wn * 32 + ((matid >> 1) << 3) + sub;  // + ng*16
    const int ncolb = ((matid & 1) << 3);                  // + ks

    const int NC = K >> 6;   // 64-wide K chunks

    stage_load(sb, 0, tid, Ah_g, Al_g, Bh_g, Bl_g, brow, bcol, K, 0);
    asm volatile("cp.async.commit_group;" ::: "memory");

    for (int kc = 0; kc < NC; kc++) {
        asm volatile("cp.async.wait_group 0;" ::: "memory");
        __syncthreads();

        if (kc + 1 < NC) {
            stage_load(sb, (kc + 1) & 1, tid, Ah_g, Al_g, Bh_g, Bl_g,
                       brow, bcol, K, (kc + 1) * 64);
            asm volatile("cp.async.commit_group;" ::: "memory");
        }

        const int s = kc & 1;
        const uint32_t sAh = sb + (uint32_t)((s * STG_E) * 2);
        const uint32_t sAl = sAh + BUF_E * 2;
        const uint32_t sBh = sAl + BUF_E * 2;
        const uint32_t sBl = sBh + BUF_E * 2;

        #pragma unroll
        for (int ks = 0; ks < 64; ks += 16) {
            uint32_t ah[2][4], al[2][4], bh[2][4], bl[2][4];
            #pragma unroll
            for (int mt = 0; mt < 2; mt++) {
                uint32_t off = (uint32_t)(((arow + mt * 16) * GSTRIDE + ks + acolb) * 2);
                ldmx4(ah[mt], sAh + off);
                ldmx4(al[mt], sAl + off);
            }
            #pragma unroll
            for (int ng = 0; ng < 2; ng++) {
                uint32_t off = (uint32_t)(((nrow + ng * 16) * GSTRIDE + ks + ncolb) * 2);
                ldmx4(bh[ng], sBh + off);
                ldmx4(bl[ng], sBl + off);
            }
            #pragma unroll
            for (int sp = 0; sp < 3; sp++) {
                #pragma unroll
                for (int mt = 0; mt < 2; mt++)
                    #pragma unroll
                    for (int nt = 0; nt < 4; nt++) {
                        const uint32_t* ap = (sp == 2) ? al[mt] : ah[mt];
                        const uint32_t* bp = (sp == 1)
                            ? &bl[nt >> 1][(nt & 1) * 2]
                            : &bh[nt >> 1][(nt & 1) * 2];
                        mma_bf16(acc[mt][nt], ap, bp);
                    }
            }
        }
        __syncthreads();
    }

    const int rg = lane >> 2;
    const int ct = lane & 3;
    #pragma unroll
    for (int mt = 0; mt < 2; mt++) {
        int r0 = brow + wm * 32 + mt * 16 + rg;
        #pragma unroll
        for (int nt = 0; nt < 4; nt++) {
            int c0 = bcol + wn * 32 + nt * 8 + ct * 2;
            float b0 = bias[c0], b1 = bias[c0 + 1];
            float v00 = acc[mt][nt][0] + b0, v01 = acc[mt][nt][1] + b1;
            float v10 = acc[mt][nt][2] + b0, v11 = acc[mt][nt][3] + b1;
            if (OM == 0) {
                *(float2*)(C + (size_t)r0 * N + c0) = make_float2(v00, v01);
                *(float2*)(C + (size_t)(r0 + 8) * N + c0) = make_float2(v10, v11);
            } else {
                __nv_bfloat16 h00 = __float2bfloat16(v00), h01 = __float2bfloat16(v01);
                __nv_bfloat16 h10 = __float2bfloat16(v10), h11 = __float2bfloat16(v11);
                *(uint32_t*)(Ch + (size_t)r0 * N + c0) = pk_bf(h00, h01);
                *(uint32_t*)(Ch + (size_t)(r0 + 8) * N + c0) = pk_bf(h10, h11);
                *(uint32_t*)(Cl + (size_t)r0 * N + c0) = pk_bf(
                    __float2bfloat16(v00 - __bfloat162float(h00)),
                    __float2bfloat16(v01 - __bfloat162float(h01)));
                *(uint32_t*)(Cl + (size_t)(r0 + 8) * N + c0) = pk_bf(
                    __float2bfloat16(v10 - __bfloat162float(h10)),
                    __float2bfloat16(v11 - __bfloat162float(h11)));
            }
        }
    }
}

// ---------------------------------------------------------------------------
// Tensor-core causal flash attention (bf16 split, fp32-class accuracy).
// (unchanged from best passing version)
// ---------------------------------------------------------------------------
#define FSTRIDE 72
#define KVBUF 4608
#define REGION 18432
#define FLASH_SMEM (2 * REGION * 2)   // 73728 bytes

__device__ __forceinline__ void load_kv(
    uint32_t sb, int region, int tid,
    const __nv_bfloat16* __restrict__ qh, const __nv_bfloat16* __restrict__ ql,
    int tokbase, int h)
{
    #pragma unroll
    for (int i = 0; i < 8; i++) {
        int idx = tid + i * 256;
        int buf = idx >> 9;
        int within = idx & 511;
        int row = within >> 3, ch = within & 7;
        const __nv_bfloat16* base = (buf & 1) ? ql : qh;
        int coff = ((buf >> 1) + 1) * 1024 + h * 64;
        const __nv_bfloat16* src = base + (size_t)(tokbase + row) * 3072 + coff + ch * 8;
        uint32_t dst = sb + (uint32_t)((region * REGION + buf * KVBUF + row * FSTRIDE + ch * 8) * 2);
        cpasync16(dst, src);
    }
}

__global__ __launch_bounds__(256)
void flash_tc(const __nv_bfloat16* __restrict__ qh, const __nv_bfloat16* __restrict__ ql,
              __nv_bfloat16* __restrict__ ath, __nv_bfloat16* __restrict__ atl)
{
    extern __shared__ __nv_bfloat16 fs[];
    const uint32_t sb = smem_u32(fs);
    const int tid = threadIdx.x, lane = tid & 31, w = tid >> 5;
    const int b = blockIdx.z, h = blockIdx.y, q0 = blockIdx.x * 128;
    const int g = lane >> 2, t = lane & 3;

    #pragma unroll
    for (int i = 0; i < 8; i++) {
        int idx = tid + i * 256;
        int sp  = idx >> 10;
        int within = idx & 1023;
        int row = within >> 3, ch = within & 7;
        const __nv_bfloat16* base = sp ? ql : qh;
        const __nv_bfloat16* src = base + (size_t)(b * T_LEN + q0 + row) * 3072 + h * 64 + ch * 8;
        uint32_t dst = sb + (uint32_t)((REGION + sp * 9216 + row * FSTRIDE + ch * 8) * 2);
        cpasync16(dst, src);
    }
    asm volatile("cp.async.commit_group;" ::: "memory");
    load_kv(sb, 0, tid, qh, ql, b * T_LEN, h);
    asm volatile("cp.async.commit_group;" ::: "memory");
    asm volatile("cp.async.wait_group 0;" ::: "memory");
    __syncthreads();

    uint32_t qa_h[4][4], qa_l[4][4];
    {
        int row = w * 16 + ((lane >> 3) & 1) * 8 + (lane & 7);
        int colh = (lane >> 4) * 8;
        #pragma unroll
        for (int ks = 0; ks < 4; ks++) {
            uint32_t addr = sb + (uint32_t)((REGION + row * FSTRIDE + ks * 16 + colh) * 2);
            ldmx4(qa_h[ks], addr);
            ldmx4(qa_l[ks], addr + 9216 * 2);
        }
    }
    __syncthreads();

    const int nt_total = q0 / 64 + 2;
    if (nt_total > 1) {
        load_kv(sb, 1, tid, qh, ql, b * T_LEN + 64, h);
        asm volatile("cp.async.commit_group;" ::: "memory");
    }

    float oacc[8][4];
    #pragma unroll
    for (int j = 0; j < 8; j++)
        #pragma unroll
        for (int e = 0; e < 4; e++) oacc[j][e] = 0.f;
    float m[2] = {-3.0e38f, -3.0e38f};
    float l[2] = {0.f, 0.f};

    const float SC = 0.125f * 1.44269504089f;

    for (int kt = 0; kt < nt_total; kt++) {
        const int k0 = kt * 64;
        if (kt + 1 < nt_total) {
            load_kv(sb, (kt + 1) & 1, tid, qh, ql, b * T_LEN + (kt + 1) * 64, h);
            asm volatile("cp.async.commit_group;" ::: "memory");
            asm volatile("cp.async.wait_group 1;" ::: "memory");
        } else {
            asm volatile("cp.async.wait_group 0;" ::: "memory");
        }
        __syncthreads();

        const int rbase = q0 + w * 16 + g;
        if (k0 <= rbase + 8) {
            const uint32_t rg2 = sb + (uint32_t)(((kt & 1) * REGION) * 2);
            const uint32_t sKh = rg2, sKl = rg2 + KVBUF * 2;
            const uint32_t sVh = rg2 + 2 * KVBUF * 2, sVl = rg2 + 3 * KVBUF * 2;

            float ps[8][4];
            #pragma unroll
            for (int j = 0; j < 8; j++)
                #pragma unroll
                for (int e = 0; e < 4; e++) ps[j][e] = 0.f;

            {
                int g8 = lane >> 3;
                int krow = 8 * (g8 >> 1) + (lane & 7);
                int kcol = (g8 & 1) * 8;
                #pragma unroll
                for (int ks = 0; ks < 4; ks++) {
                    uint32_t kbh[4][4], kbl[4][4];
                    #pragma unroll
                    for (int j2 = 0; j2 < 4; j2++) {
                        uint32_t off = (uint32_t)(((16 * j2 + krow) * FSTRIDE + 16 * ks + kcol) * 2);
                        ldmx4(kbh[j2], sKh + off);
                        ldmx4(kbl[j2], sKl + off);
                    }
                    #pragma unroll
                    for (int sp = 0; sp < 3; sp++) {
                        const uint32_t* qa = (sp == 2) ? qa_l[ks] : qa_h[ks];
                        #pragma unroll
                        for (int j = 0; j < 8; j++) {
                            const uint32_t* bp = (sp == 1)
                                ? &kbl[j >> 1][(j & 1) * 2]
                                : &kbh[j >> 1][(j & 1) * 2];
                            mma_bf16(ps[j], qa, bp);
                        }
                    }
                }
            }

            if (k0 + 63 > q0 + w * 16) {
                #pragma unroll
                for (int j = 0; j < 8; j++)
                    #pragma unroll
                    for (int e = 0; e < 4; e++) {
                        int col = k0 + j * 8 + t * 2 + (e & 1);
                        int row = rbase + (e >> 1) * 8;
                        ps[j][e] = (col <= row) ? ps[j][e] * SC : -1.0e30f;
                    }
            } else {
                #pragma unroll
                for (int j = 0; j < 8; j++)
                    #pragma unroll
                    for (int e = 0; e < 4; e++) ps[j][e] *= SC;
            }

            float tmax[2] = {-3.0e38f, -3.0e38f};
            #pragma unroll
            for (int j = 0; j < 8; j++) {
                tmax[0] = fmaxf(tmax[0], fmaxf(ps[j][0], ps[j][1]));
                tmax[1] = fmaxf(tmax[1], fmaxf(ps[j][2], ps[j][3]));
            }
            #pragma unroll
            for (int r = 0; r < 2; r++) {
                tmax[r] = fmaxf(tmax[r], __shfl_xor_sync(0xffffffffu, tmax[r], 1));
                tmax[r] = fmaxf(tmax[r], __shfl_xor_sync(0xffffffffu, tmax[r], 2));
            }
            float corr[2];
            #pragma unroll
            for (int r = 0; r < 2; r++) {
                float mn = fmaxf(m[r], tmax[r]);
                corr[r] = ex2(m[r] - mn);
                m[r] = mn;
            }
            float rsum[2] = {0.f, 0.f};
            #pragma unroll
            for (int j = 0; j < 8; j++)
                #pragma unroll
                for (int e = 0; e < 4; e++) {
                    float p = ex2(ps[j][e] - m[e >> 1]);
                    ps[j][e] = p;
                    rsum[e >> 1] += p;
                }
            #pragma unroll
            for (int r = 0; r < 2; r++) {
                rsum[r] += __shfl_xor_sync(0xffffffffu, rsum[r], 1);
                rsum[r] += __shfl_xor_sync(0xffffffffu, rsum[r], 2);
                l[r] = l[r] * corr[r] + rsum[r];
            }
            #pragma unroll
            for (int j = 0; j < 8; j++)
                #pragma unroll
                for (int e = 0; e < 4; e++) oacc[j][e] *= corr[e >> 1];

            {
                int g8 = lane >> 3;
                int vrow = (g8 & 1) * 8 + (lane & 7);
                int vcol = (g8 >> 1) * 8;
                #pragma unroll
                for (int ks = 0; ks < 4; ks++) {
                    uint32_t pah[4], pal[4];
                    #pragma unroll
                    for (int q2 = 0; q2 < 2; q2++) {
                        const float* pv = ps[2 * ks + q2];
                        #pragma unroll
                        for (int rh = 0; rh < 2; rh++) {
                            float p0 = pv[rh * 2 + 0], p1 = pv[rh * 2 + 1];
                            __nv_bfloat16 h0 = __float2bfloat16(p0);
                            __nv_bfloat16 h1 = __float2bfloat16(p1);
                            pah[q2 * 2 + rh] = pk_bf(h0, h1);
                            pal[q2 * 2 + rh] = pk_bf(
                                __float2bfloat16(p0 - __bfloat162float(h0)),
                                __float2bfloat16(p1 - __bfloat162float(h1)));
                        }
                    }
                    uint32_t vbh[4][4], vbl[4][4];
                    #pragma unroll
                    for (int j2 = 0; j2 < 4; j2++) {
                        uint32_t off = (uint32_t)(((16 * ks + vrow) * FSTRIDE + 16 * j2 + vcol) * 2);
                        ldmx4t(vbh[j2], sVh + off);
                        ldmx4t(vbl[j2], sVl + off);
                    }
                    #pragma unroll
                    for (int sp = 0; sp < 3; sp++) {
                        const uint32_t* pa = (sp == 2) ? pal : pah;
                        #pragma unroll
                        for (int dn = 0; dn < 8; dn++) {
                            const uint32_t* bp = (sp == 1)
                                ? &vbl[dn >> 1][(dn & 1) * 2]
                                : &vbh[dn >> 1][(dn & 1) * 2];
                            mma_bf16(oacc[dn], pa, bp);
                        }
                    }
                }
            }
        }
        __syncthreads();
    }

    float inv[2] = {1.f / l[0], 1.f / l[1]};
    #pragma unroll
    for (int rh = 0; rh < 2; rh++) {
        int tok = b * T_LEN + q0 + w * 16 + g + rh * 8;
        #pragma unroll
        for (int j = 0; j < 8; j++) {
            int col = h * 64 + j * 8 + t * 2;
            float v0 = oacc[j][rh * 2 + 0] * inv[rh];
            float v1 = oacc[j][rh * 2 + 1] * inv[rh];
            __nv_bfloat16 h0 = __float2bfloat16(v0), h1 = __float2bfloat16(v1);
            *(uint32_t*)(ath + (size_t)tok * D_MODEL + col) = pk_bf(h0, h1);
            *(uint32_t*)(atl + (size_t)tok * D_MODEL + col) = pk_bf(
                __float2bfloat16(v0 - __bfloat162float(h0)),
                __float2bfloat16(v1 - __bfloat162float(h1)));
        }
    }
}

// ---------------------------------------------------------------------------
extern "C" void kernel_launch(void* const* d_in, const int* in_sizes, int n_in,
                              void* d_out, int out_size)
{
    const float *x = nullptr, *w_qkv = nullptr, *b_qkv = nullptr,
                *w_out = nullptr, *b_out = nullptr;
    for (int i = 0; i < n_in; i++) {
        switch (in_sizes[i]) {
            case 8388608: x     = (const float*)d_in[i]; break;
            case 3145728: w_qkv = (const float*)d_in[i]; break;
            case 3072:    b_qkv = (const float*)d_in[i]; break;
            case 1048576: w_out = (const float*)d_in[i]; break;
            case 1024:    b_out = (const float*)d_in[i]; break;
            default: break;
        }
    }
    float* out = (float*)d_out;

    __nv_bfloat16 *xh, *xl, *wqh, *wql, *woh, *wol, *qkvh, *qkvl, *ath, *atl;
    cudaGetSymbolAddress((void**)&xh, g_xh);   cudaGetSymbolAddress((void**)&xl, g_xl);
    cudaGetSymbolAddress((void**)&wqh, g_wqh); cudaGetSymbolAddress((void**)&wql, g_wql);
    cudaGetSymbolAddress((void**)&woh, g_woh); cudaGetSymbolAddress((void**)&wol, g_wol);
    cudaGetSymbolAddress((void**)&qkvh, g_qkvh); cudaGetSymbolAddress((void**)&qkvl, g_qkvl);
    cudaGetSymbolAddress((void**)&ath, g_ath); cudaGetSymbolAddress((void**)&atl, g_atl);

    cudaFuncSetAttribute(gemm_bf16split<0>, cudaFuncAttributeMaxDynamicSharedMemorySize, GEMM_SMEM);
    cudaFuncSetAttribute(gemm_bf16split<1>, cudaFuncAttributeMaxDynamicSharedMemorySize, GEMM_SMEM);
    cudaFuncSetAttribute(flash_tc, cudaFuncAttributeMaxDynamicSharedMemorySize, FLASH_SMEM);

    // 0) pre-split inputs
    int n4x = TOKENS * D_MODEL / 4;
    split_bf16<<<(n4x + 255) / 256, 256>>>(x, xh, xl, n4x);
    int n4q = 3 * D_MODEL * D_MODEL / 4;
    split_bf16<<<(n4q + 255) / 256, 256>>>(w_qkv, wqh, wql, n4q);
    int n4o = D_MODEL * D_MODEL / 4;
    split_bf16<<<(n4o + 255) / 256, 256>>>(w_out, woh, wol, n4o);

    // 1) QKV projection -> split bf16 qkv
    gemm_bf16split<1><<<dim3(3 * D_MODEL / 128, TOKENS / 128), 512, GEMM_SMEM>>>(
        xh, xl, wqh, wql, b_qkv, nullptr, qkvh, qkvl, TOKENS, 3 * D_MODEL, D_MODEL);

    // 2) TC causal flash attention -> split bf16 attn
    flash_tc<<<dim3(T_LEN / 128, N_HEADS, B_SIZE), 256, FLASH_SMEM>>>(qkvh, qkvl, ath, atl);

    // 3) Output projection -> fp32 d_out
    gemm_bf16split<0><<<dim3(D_MODEL / 128, TOKENS / 128), 512, GEMM_SMEM>>>(
        ath, atl, woh, wol, b_out, out, nullptr, nullptr, TOKENS, D_MODEL, D_MODEL);
}

// round 14
// speedup vs baseline: 5.9016x; 1.3649x over previous
#include <cuda_runtime.h>
#include <cuda_fp16.h>
#include <math.h>
#include <stdint.h>

#define D_MODEL 1024
#define N_HEADS 16
#define HEAD_DIM 64
#define B_SIZE 4
#define T_LEN 2048
#define TOKENS (B_SIZE * T_LEN)   // 8192

// ---------------- scratch (device globals; allocation-free) ----------------
__device__ __half g_xh[(size_t)TOKENS * D_MODEL], g_xl[(size_t)TOKENS * D_MODEL];
__device__ __half g_wqh[(size_t)3 * D_MODEL * D_MODEL], g_wql[(size_t)3 * D_MODEL * D_MODEL];
__device__ __half g_woh[(size_t)D_MODEL * D_MODEL], g_wol[(size_t)D_MODEL * D_MODEL];
__device__ __half g_qkvh[(size_t)TOKENS * 3 * D_MODEL], g_qkvl[(size_t)TOKENS * 3 * D_MODEL];
__device__ __half g_ath[(size_t)TOKENS * D_MODEL], g_atl[(size_t)TOKENS * D_MODEL];

// ---------------------------- small helpers --------------------------------
__device__ __forceinline__ uint32_t smem_u32(const void* p) {
    uint32_t a;
    asm("{ .reg .u64 t; cvta.to.shared.u64 t, %1; cvt.u32.u64 %0, t; }"
        : "=r"(a) : "l"(p));
    return a;
}
__device__ __forceinline__ uint32_t pk_hf(__half a, __half b) {
    return (uint32_t)__half_as_ushort(a) | ((uint32_t)__half_as_ushort(b) << 16);
}
__device__ __forceinline__ void mma_f16(float* c, const uint32_t* a, const uint32_t* b) {
    asm volatile(
        "mma.sync.aligned.m16n8k16.row.col.f32.f16.f16.f32 "
        "{%0,%1,%2,%3}, {%4,%5,%6,%7}, {%8,%9}, {%0,%1,%2,%3};"
        : "+f"(c[0]), "+f"(c[1]), "+f"(c[2]), "+f"(c[3])
        : "r"(a[0]), "r"(a[1]), "r"(a[2]), "r"(a[3]), "r"(b[0]), "r"(b[1]));
}
__device__ __forceinline__ void ldmx4(uint32_t r[4], uint32_t addr) {
    asm volatile("ldmatrix.sync.aligned.m8n8.x4.shared.b16 {%0,%1,%2,%3}, [%4];"
        : "=r"(r[0]), "=r"(r[1]), "=r"(r[2]), "=r"(r[3]) : "r"(addr));
}
__device__ __forceinline__ void ldmx4t(uint32_t r[4], uint32_t addr) {
    asm volatile("ldmatrix.sync.aligned.m8n8.x4.trans.shared.b16 {%0,%1,%2,%3}, [%4];"
        : "=r"(r[0]), "=r"(r[1]), "=r"(r[2]), "=r"(r[3]) : "r"(addr));
}
__device__ __forceinline__ void cpasync16(uint32_t dst, const void* src) {
    asm volatile("cp.async.cg.shared.global [%0], [%1], 16;" :: "r"(dst), "l"(src) : "memory");
}
__device__ __forceinline__ float ex2(float x) {
    float y; asm("ex2.approx.f32 %0, %1;" : "=f"(y) : "f"(x)); return y;
}

// -------------------- pre-split: fp32 -> fp16 hi + lo ----------------------
__global__ __launch_bounds__(256)
void split_f16(const float* __restrict__ src, __half* __restrict__ hi,
               __half* __restrict__ lo, int n4)
{
    int i = blockIdx.x * 256 + threadIdx.x;
    if (i >= n4) return;
    float4 f = ((const float4*)src)[i];
    float v[4] = {f.x, f.y, f.z, f.w};
    __half h[4], l[4];
    #pragma unroll
    for (int j = 0; j < 4; j++) {
        h[j] = __float2half(v[j]);
        l[j] = __float2half(v[j] - __half2float(h[j]));
    }
    ((uint2*)hi)[i] = make_uint2(pk_hf(h[0], h[1]), pk_hf(h[2], h[3]));
    ((uint2*)lo)[i] = make_uint2(pk_hf(l[0], l[1]), pk_hf(l[2], l[3]));
}

// ---------------------------------------------------------------------------
// fp16 2-pass GEMM: C[M,N] = A@W^T + bias, A exact (hi+lo), W ~ fp16 hi only.
// 512 threads (16 warps 4x4, warp tile 32x32), BK=64, 2-stage cp.async,
// stride-72 smem rows. OM=0: fp32 out; OM=1: fp16 hi/lo out.
// ---------------------------------------------------------------------------
#define GSTRIDE 72
#define BUF_E (128 * GSTRIDE)      // 9216 el per buffer
#define STG_E (3 * BUF_E)          // 27648 el per stage (Ah, Al, Bh)
#define GEMM_SMEM (2 * STG_E * 2)  // 110592 bytes

__device__ __forceinline__ void stage_load(
    uint32_t sb, int s, int tid,
    const __half* __restrict__ Ah_g, const __half* __restrict__ Al_g,
    const __half* __restrict__ Bh_g,
    int brow, int bcol, int K, int k0)
{
    // 3 buffers * 128 rows * 8 chunks = 3072 16B chunks; 512 thr * 6 iters
    #pragma unroll
    for (int i = 0; i < 6; i++) {
        int c      = tid + i * 512;      // 0..3071
        int buf    = c >> 10;            // 0:Ah 1:Al 2:Bh
        int within = c & 1023;
        int row    = within >> 3;        // 0..127
        int ch     = within & 7;         // 0..7 (8 el each)
        const __half* g = (buf == 0) ? Ah_g : (buf == 1) ? Al_g : Bh_g;
        int gr = ((buf < 2) ? brow : bcol) + row;
        const __half* src = g + (size_t)gr * K + k0 + ch * 8;
        uint32_t dst = sb + (uint32_t)((s * STG_E + buf * BUF_E + row * GSTRIDE + ch * 8) * 2);
        cpasync16(dst, src);
    }
}

template<int OM>
__global__ __launch_bounds__(512, 1)
void gemm_f16split(const __half* __restrict__ Ah_g, const __half* __restrict__ Al_g,
                   const __half* __restrict__ Bh_g,
                   const float* __restrict__ bias, float* __restrict__ C,
                   __half* __restrict__ Ch, __half* __restrict__ Cl,
                   int M, int N, int K)
{
    extern __shared__ __half sm[];
    const uint32_t sb   = smem_u32(sm);
    const int tid  = threadIdx.x;
    const int lane = tid & 31;
    const int w    = tid >> 5;          // 0..15
    const int wm   = w >> 2;            // 0..3
    const int wn   = w & 3;             // 0..3
    const int sub  = lane & 7;
    const int matid = lane >> 3;
    const int brow = blockIdx.y * 128;
    const int bcol = blockIdx.x * 128;

    float acc[2][4][4];
    #pragma unroll
    for (int i = 0; i < 2; i++)
        #pragma unroll
        for (int j = 0; j < 4; j++)
            #pragma unroll
            for (int e = 0; e < 4; e++) acc[i][j][e] = 0.f;

    const int arow = wm * 32 + ((matid & 1) << 3) + sub;
    const int acolb = ((matid >> 1) << 3);
    const int nrow = wn * 32 + ((matid >> 1) << 3) + sub;
    const int ncolb = ((matid & 1) << 3);

    const int NC = K >> 6;   // 64-wide K chunks

    stage_load(sb, 0, tid, Ah_g, Al_g, Bh_g, brow, bcol, K, 0);
    asm volatile("cp.async.commit_group;" ::: "memory");

    for (int kc = 0; kc < NC; kc++) {
        asm volatile("cp.async.wait_group 0;" ::: "memory");
        __syncthreads();

        if (kc + 1 < NC) {
            stage_load(sb, (kc + 1) & 1, tid, Ah_g, Al_g, Bh_g,
                       brow, bcol, K, (kc + 1) * 64);
            asm volatile("cp.async.commit_group;" ::: "memory");
        }

        const int s = kc & 1;
        const uint32_t sAh = sb + (uint32_t)((s * STG_E) * 2);
        const uint32_t sAl = sAh + BUF_E * 2;
        const uint32_t sBh = sAl + BUF_E * 2;

        #pragma unroll
        for (int ks = 0; ks < 64; ks += 16) {
            uint32_t ah[2][4], al[2][4], bh[2][4];
            #pragma unroll
            for (int mt = 0; mt < 2; mt++) {
                uint32_t off = (uint32_t)(((arow + mt * 16) * GSTRIDE + ks + acolb) * 2);
                ldmx4(ah[mt], sAh + off);
                ldmx4(al[mt], sAl + off);
            }
            #pragma unroll
            for (int ng = 0; ng < 2; ng++) {
                uint32_t off = (uint32_t)(((nrow + ng * 16) * GSTRIDE + ks + ncolb) * 2);
                ldmx4(bh[ng], sBh + off);
            }
            #pragma unroll
            for (int sp = 0; sp < 2; sp++) {
                #pragma unroll
                for (int mt = 0; mt < 2; mt++)
                    #pragma unroll
                    for (int nt = 0; nt < 4; nt++) {
                        const uint32_t* ap = sp ? al[mt] : ah[mt];
                        mma_f16(acc[mt][nt], ap, &bh[nt >> 1][(nt & 1) * 2]);
                    }
            }
        }
        __syncthreads();
    }

    const int rg = lane >> 2;
    const int ct = lane & 3;
    #pragma unroll
    for (int mt = 0; mt < 2; mt++) {
        int r0 = brow + wm * 32 + mt * 16 + rg;
        #pragma unroll
        for (int nt = 0; nt < 4; nt++) {
            int c0 = bcol + wn * 32 + nt * 8 + ct * 2;
            float b0 = bias[c0], b1 = bias[c0 + 1];
            float v00 = acc[mt][nt][0] + b0, v01 = acc[mt][nt][1] + b1;
            float v10 = acc[mt][nt][2] + b0, v11 = acc[mt][nt][3] + b1;
            if (OM == 0) {
                *(float2*)(C + (size_t)r0 * N + c0) = make_float2(v00, v01);
                *(float2*)(C + (size_t)(r0 + 8) * N + c0) = make_float2(v10, v11);
            } else {
                __half h00 = __float2half(v00), h01 = __float2half(v01);
                __half h10 = __float2half(v10), h11 = __float2half(v11);
                *(uint32_t*)(Ch + (size_t)r0 * N + c0) = pk_hf(h00, h01);
                *(uint32_t*)(Ch + (size_t)(r0 + 8) * N + c0) = pk_hf(h10, h11);
                *(uint32_t*)(Cl + (size_t)r0 * N + c0) = pk_hf(
                    __float2half(v00 - __half2float(h00)),
                    __float2half(v01 - __half2float(h01)));
                *(uint32_t*)(Cl + (size_t)(r0 + 8) * N + c0) = pk_hf(
                    __float2half(v10 - __half2float(h10)),
                    __float2half(v11 - __half2float(h11)));
            }
        }
    }
}

// ---------------------------------------------------------------------------
// fp16 2-pass causal flash attention. Q/P exact (hi+lo), K/V fp16 hi only.
// Block: 128 q rows x one (b,h). 256 thr, 8 warps x 16 rows.
// ---------------------------------------------------------------------------
#define FSTRIDE 72
#define KVBUF 4608            // 64*72 el per buffer
#define REGION 9216           // per stage: Kh + Vh
#define QOFF 18432            // Q hi/lo planes after 2 KV stages
#define FLASH_SMEM ((QOFF + 2 * 9216) * 2)   // 73728 bytes

__device__ __forceinline__ void load_kv(
    uint32_t sb, int region, int tid,
    const __half* __restrict__ qh, int tokbase, int h)
{
    // 2 buffers (Kh, Vh) * 64 rows * 8 chunks = 1024; 256 thr * 4 iters
    #pragma unroll
    for (int i = 0; i < 4; i++) {
        int idx = tid + i * 256;          // 0..1023
        int buf = idx >> 9;               // 0:Kh 1:Vh
        int within = idx & 511;
        int row = within >> 3, ch = within & 7;
        const __half* src = qh + (size_t)(tokbase + row) * 3072 + (buf + 1) * 1024 + h * 64 + ch * 8;
        uint32_t dst = sb + (uint32_t)((region * REGION + buf * KVBUF + row * FSTRIDE + ch * 8) * 2);
        cpasync16(dst, src);
    }
}

__global__ __launch_bounds__(256)
void flash_tc(const __half* __restrict__ qh, const __half* __restrict__ ql,
              __half* __restrict__ ath, __half* __restrict__ atl)
{
    extern __shared__ __half fs[];
    const uint32_t sb = smem_u32(fs);
    const int tid = threadIdx.x, lane = tid & 31, w = tid >> 5;
    const int b = blockIdx.z, h = blockIdx.y, q0 = blockIdx.x * 128;
    const int g = lane >> 2, t = lane & 3;

    // ---- stage Q hi/lo (dedicated area) + KV tile 0 (region 0) ----
    #pragma unroll
    for (int i = 0; i < 8; i++) {
        int idx = tid + i * 256;          // 0..2047
        int sp  = idx >> 10;              // 0 hi, 1 lo
        int within = idx & 1023;
        int row = within >> 3, ch = within & 7;
        const __half* base = sp ? ql : qh;
        const __half* src = base + (size_t)(b * T_LEN + q0 + row) * 3072 + h * 64 + ch * 8;
        uint32_t dst = sb + (uint32_t)((QOFF + sp * 9216 + row * FSTRIDE + ch * 8) * 2);
        cpasync16(dst, src);
    }
    asm volatile("cp.async.commit_group;" ::: "memory");
    load_kv(sb, 0, tid, qh, b * T_LEN, h);
    asm volatile("cp.async.commit_group;" ::: "memory");
    asm volatile("cp.async.wait_group 0;" ::: "memory");
    __syncthreads();

    // ---- Q fragments (registers, whole kernel) ----
    uint32_t qa_h[4][4], qa_l[4][4];
    {
        int row = w * 16 + ((lane >> 3) & 1) * 8 + (lane & 7);
        int colh = (lane >> 4) * 8;
        #pragma unroll
        for (int ks = 0; ks < 4; ks++) {
            uint32_t addr = sb + (uint32_t)((QOFF + row * FSTRIDE + ks * 16 + colh) * 2);
            ldmx4(qa_h[ks], addr);
            ldmx4(qa_l[ks], addr + 9216 * 2);
        }
    }

    const int nt_total = q0 / 64 + 2;

    float oacc[8][4];
    #pragma unroll
    for (int j = 0; j < 8; j++)
        #pragma unroll
        for (int e = 0; e < 4; e++) oacc[j][e] = 0.f;
    float m[2] = {-3.0e38f, -3.0e38f};
    float l[2] = {0.f, 0.f};

    const float SC = 0.125f * 1.44269504089f;

    for (int kt = 0; kt < nt_total; kt++) {
        const int k0 = kt * 64;
        if (kt + 1 < nt_total) {
            load_kv(sb, (kt + 1) & 1, tid, qh, b * T_LEN + (kt + 1) * 64, h);
            asm volatile("cp.async.commit_group;" ::: "memory");
            asm volatile("cp.async.wait_group 1;" ::: "memory");
        } else {
            asm volatile("cp.async.wait_group 0;" ::: "memory");
        }
        __syncthreads();

        const int rbase = q0 + w * 16 + g;
        if (k0 <= rbase + 8) {
            const uint32_t rg2 = sb + (uint32_t)(((kt & 1) * REGION) * 2);
            const uint32_t sKh = rg2, sVh = rg2 + KVBUF * 2;

            // ---- S = Q K^T (2-pass: Qh*Kh + Ql*Kh) ----
            float ps[8][4];
            #pragma unroll
            for (int j = 0; j < 8; j++)
                #pragma unroll
                for (int e = 0; e < 4; e++) ps[j][e] = 0.f;

            {
                int g8 = lane >> 3;
                int krow = 8 * (g8 >> 1) + (lane & 7);
                int kcol = (g8 & 1) * 8;
                #pragma unroll
                for (int ks = 0; ks < 4; ks++) {
                    uint32_t kbh[4][4];
                    #pragma unroll
                    for (int j2 = 0; j2 < 4; j2++) {
                        uint32_t off = (uint32_t)(((16 * j2 + krow) * FSTRIDE + 16 * ks + kcol) * 2);
                        ldmx4(kbh[j2], sKh + off);
                    }
                    #pragma unroll
                    for (int sp = 0; sp < 2; sp++) {
                        const uint32_t* qa = sp ? qa_l[ks] : qa_h[ks];
                        #pragma unroll
                        for (int j = 0; j < 8; j++)
                            mma_f16(ps[j], qa, &kbh[j >> 1][(j & 1) * 2]);
                    }
                }
            }

            // ---- scale + causal mask ----
            if (k0 + 63 > q0 + w * 16) {
                #pragma unroll
                for (int j = 0; j < 8; j++)
                    #pragma unroll
                    for (int e = 0; e < 4; e++) {
                        int col = k0 + j * 8 + t * 2 + (e & 1);
                        int row = rbase + (e >> 1) * 8;
                        ps[j][e] = (col <= row) ? ps[j][e] * SC : -1.0e30f;
                    }
            } else {
                #pragma unroll
                for (int j = 0; j < 8; j++)
                    #pragma unroll
                    for (int e = 0; e < 4; e++) ps[j][e] *= SC;
            }

            // ---- online softmax ----
            float tmax[2] = {-3.0e38f, -3.0e38f};
            #pragma unroll
            for (int j = 0; j < 8; j++) {
                tmax[0] = fmaxf(tmax[0], fmaxf(ps[j][0], ps[j][1]));
                tmax[1] = fmaxf(tmax[1], fmaxf(ps[j][2], ps[j][3]));
            }
            #pragma unroll
            for (int r = 0; r < 2; r++) {
                tmax[r] = fmaxf(tmax[r], __shfl_xor_sync(0xffffffffu, tmax[r], 1));
                tmax[r] = fmaxf(tmax[r], __shfl_xor_sync(0xffffffffu, tmax[r], 2));
            }
            float corr[2];
            #pragma unroll
            for (int r = 0; r < 2; r++) {
                float mn = fmaxf(m[r], tmax[r]);
                corr[r] = ex2(m[r] - mn);
                m[r] = mn;
            }
            float rsum[2] = {0.f, 0.f};
            #pragma unroll
            for (int j = 0; j < 8; j++)
                #pragma unroll
                for (int e = 0; e < 4; e++) {
                    float p = ex2(ps[j][e] - m[e >> 1]);
                    ps[j][e] = p;
                    rsum[e >> 1] += p;
                }
            #pragma unroll
            for (int r = 0; r < 2; r++) {
                rsum[r] += __shfl_xor_sync(0xffffffffu, rsum[r], 1);
                rsum[r] += __shfl_xor_sync(0xffffffffu, rsum[r], 2);
                l[r] = l[r] * corr[r] + rsum[r];
            }
            #pragma unroll
            for (int j = 0; j < 8; j++)
                #pragma unroll
                for (int e = 0; e < 4; e++) oacc[j][e] *= corr[e >> 1];

            // ---- O += P V (2-pass: Ph*Vh + Pl*Vh) ----
            {
                int g8 = lane >> 3;
                int vrow = (g8 & 1) * 8 + (lane & 7);
                int vcol = (g8 >> 1) * 8;
                #pragma unroll
                for (int ks = 0; ks < 4; ks++) {
                    uint32_t pah[4], pal[4];
                    #pragma unroll
                    for (int q2 = 0; q2 < 2; q2++) {
                        const float* pv = ps[2 * ks + q2];
                        #pragma unroll
                        for (int rh = 0; rh < 2; rh++) {
                            float p0 = pv[rh * 2 + 0], p1 = pv[rh * 2 + 1];
                            __half h0 = __float2half(p0);
                            __half h1 = __float2half(p1);
                            pah[q2 * 2 + rh] = pk_hf(h0, h1);
                            pal[q2 * 2 + rh] = pk_hf(
                                __float2half(p0 - __half2float(h0)),
                                __float2half(p1 - __half2float(h1)));
                        }
                    }
                    uint32_t vbh[4][4];
                    #pragma unroll
                    for (int j2 = 0; j2 < 4; j2++) {
                        uint32_t off = (uint32_t)(((16 * ks + vrow) * FSTRIDE + 16 * j2 + vcol) * 2);
                        ldmx4t(vbh[j2], sVh + off);
                    }
                    #pragma unroll
                    for (int sp = 0; sp < 2; sp++) {
                        const uint32_t* pa = sp ? pal : pah;
                        #pragma unroll
                        for (int dn = 0; dn < 8; dn++)
                            mma_f16(oacc[dn], pa, &vbh[dn >> 1][(dn & 1) * 2]);
                    }
                }
            }
        }
        __syncthreads();
    }

    // ---- epilogue: normalize, split fp16, store ----
    float inv[2] = {1.f / l[0], 1.f / l[1]};
    #pragma unroll
    for (int rh = 0; rh < 2; rh++) {
        int tok = b * T_LEN + q0 + w * 16 + g + rh * 8;
        #pragma unroll
        for (int j = 0; j < 8; j++) {
            int col = h * 64 + j * 8 + t * 2;
            float v0 = oacc[j][rh * 2 + 0] * inv[rh];
            float v1 = oacc[j][rh * 2 + 1] * inv[rh];
            __half h0 = __float2half(v0), h1 = __float2half(v1);
            *(uint32_t*)(ath + (size_t)tok * D_MODEL + col) = pk_hf(h0, h1);
            *(uint32_t*)(atl + (size_t)tok * D_MODEL + col) = pk_hf(
                __float2half(v0 - __half2float(h0)),
                __float2half(v1 - __half2float(h1)));
        }
    }
}

// ---------------------------------------------------------------------------
extern "C" void kernel_launch(void* const* d_in, const int* in_sizes, int n_in,
                              void* d_out, int out_size)
{
    const float *x = nullptr, *w_qkv = nullptr, *b_qkv = nullptr,
                *w_out = nullptr, *b_out = nullptr;
    for (int i = 0; i < n_in; i++) {
        switch (in_sizes[i]) {
            case 8388608: x     = (const float*)d_in[i]; break;
            case 3145728: w_qkv = (const float*)d_in[i]; break;
            case 3072:    b_qkv = (const float*)d_in[i]; break;
            case 1048576: w_out = (const float*)d_in[i]; break;
            case 1024:    b_out = (const float*)d_in[i]; break;
            default: break;
        }
    }
    float* out = (float*)d_out;

    __half *xh, *xl, *wqh, *wql, *woh, *wol, *qkvh, *qkvl, *ath, *atl;
    cudaGetSymbolAddress((void**)&xh, g_xh);   cudaGetSymbolAddress((void**)&xl, g_xl);
    cudaGetSymbolAddress((void**)&wqh, g_wqh); cudaGetSymbolAddress((void**)&wql, g_wql);
    cudaGetSymbolAddress((void**)&woh, g_woh); cudaGetSymbolAddress((void**)&wol, g_wol);
    cudaGetSymbolAddress((void**)&qkvh, g_qkvh); cudaGetSymbolAddress((void**)&qkvl, g_qkvl);
    cudaGetSymbolAddress((void**)&ath, g_ath); cudaGetSymbolAddress((void**)&atl, g_atl);

    cudaFuncSetAttribute(gemm_f16split<0>, cudaFuncAttributeMaxDynamicSharedMemorySize, GEMM_SMEM);
    cudaFuncSetAttribute(gemm_f16split<1>, cudaFuncAttributeMaxDynamicSharedMemorySize, GEMM_SMEM);
    cudaFuncSetAttribute(flash_tc, cudaFuncAttributeMaxDynamicSharedMemorySize, FLASH_SMEM);

    // 0) pre-split inputs (x needs hi+lo; weights only hi is consumed)
    int n4x = TOKENS * D_MODEL / 4;
    split_f16<<<(n4x + 255) / 256, 256>>>(x, xh, xl, n4x);
    int n4q = 3 * D_MODEL * D_MODEL / 4;
    split_f16<<<(n4q + 255) / 256, 256>>>(w_qkv, wqh, wql, n4q);
    int n4o = D_MODEL * D_MODEL / 4;
    split_f16<<<(n4o + 255) / 256, 256>>>(w_out, woh, wol, n4o);

    // 1) QKV projection -> split fp16 qkv
    gemm_f16split<1><<<dim3(3 * D_MODEL / 128, TOKENS / 128), 512, GEMM_SMEM>>>(
        xh, xl, wqh, b_qkv, nullptr, qkvh, qkvl, TOKENS, 3 * D_MODEL, D_MODEL);

    // 2) TC causal flash attention -> split fp16 attn
    flash_tc<<<dim3(T_LEN / 128, N_HEADS, B_SIZE), 256, FLASH_SMEM>>>(qkvh, qkvl, ath, atl);

    // 3) Output projection -> fp32 d_out
    gemm_f16split<0><<<dim3(D_MODEL / 128, TOKENS / 128), 512, GEMM_SMEM>>>(
        ath, atl, woh, b_out, out, nullptr, nullptr, TOKENS, D_MODEL, D_MODEL);
}